// round 6
// baseline (speedup 1.0000x reference)
#include <cuda_runtime.h>
#include <math.h>

#define N_TOK 4301
#define NP    4201
#define ND    100
#define D     768
#define H     12
#define HD    64
#define QSCALE 0.125f

// Scratch (allocation-free rule: __device__ globals)
__device__ float g_q[(size_t)N_TOK * D];
__device__ float g_k[(size_t)N_TOK * D];
__device__ float g_v[(size_t)N_TOK * D];
__device__ float g_o[(size_t)N_TOK * D];

// ---------------------------------------------------------------------------
// tf32 helpers
// ---------------------------------------------------------------------------
__device__ __forceinline__ unsigned f2tf32(float x) {
    unsigned u;
    asm("cvt.rna.tf32.f32 %0, %1;" : "=r"(u) : "f"(x));
    return u;
}
__device__ __forceinline__ float tf32r(float x) {
    return __uint_as_float(f2tf32(x));
}
__device__ __forceinline__ void mma_tf32(float* c,
    unsigned a0, unsigned a1, unsigned a2, unsigned a3,
    unsigned b0, unsigned b1)
{
    asm volatile(
        "mma.sync.aligned.m16n8k8.row.col.f32.tf32.tf32.f32 "
        "{%0,%1,%2,%3}, {%4,%5,%6,%7}, {%8,%9}, {%0,%1,%2,%3};"
        : "+f"(c[0]), "+f"(c[1]), "+f"(c[2]), "+f"(c[3])
        : "r"(a0), "r"(a1), "r"(a2), "r"(a3), "r"(b0), "r"(b1));
}

// ---------------------------------------------------------------------------
// GEMM tile body: C[tile] = (A @ W^T + bias) * scale
// Block 256 thr (8 warps, 2m x 4n), tile 128x128, BK=16.
// Ping-pong double-buffered smem: ONE barrier per K-iter, LDG overlapped.
// ---------------------------------------------------------------------------
#define GBK 16
#define GAS 20   // As stride (floats)
#define GBS 20   // Bs stride

struct GemmSmem {
    float As[2][128 * GAS];
    float Bs[2][128 * GBS];
};

__device__ __forceinline__ void gemm_tile_body(
    const float* __restrict__ A,
    const float* __restrict__ W,
    const float* __restrict__ bias,
    float* __restrict__ C,
    int m0, int n0, int M, float scale,
    GemmSmem& s)
{
    const int tid = threadIdx.x;
    const int w = tid >> 5;
    const int l = tid & 31;
    const int g = l >> 2;
    const int t = l & 3;
    const int wm = (w >> 2) * 64;
    const int wn = (w & 3) * 32;

    int row_[2], c4_[2];
#pragma unroll
    for (int it = 0; it < 2; it++) {
        int slot = tid + 256 * it;
        row_[it] = slot >> 2;
        c4_[it]  = (slot & 3) * 4;
    }

    float acc[4][4][4];
#pragma unroll
    for (int i = 0; i < 4; i++)
#pragma unroll
        for (int j = 0; j < 4; j++)
#pragma unroll
            for (int r = 0; r < 4; r++) acc[i][j][r] = 0.f;

    // prologue: load + store k0 = 0 into buffer 0
    {
#pragma unroll
        for (int it = 0; it < 2; it++) {
            float4 av = make_float4(0.f, 0.f, 0.f, 0.f);
            if (m0 + row_[it] < M)
                av = *(const float4*)(A + (size_t)(m0 + row_[it]) * D + c4_[it]);
            float4 bv = *(const float4*)(W + (size_t)(n0 + row_[it]) * D + c4_[it]);
            av.x = tf32r(av.x); av.y = tf32r(av.y);
            av.z = tf32r(av.z); av.w = tf32r(av.w);
            bv.x = tf32r(bv.x); bv.y = tf32r(bv.y);
            bv.z = tf32r(bv.z); bv.w = tf32r(bv.w);
            *(float4*)(s.As[0] + row_[it] * GAS + c4_[it]) = av;
            *(float4*)(s.Bs[0] + row_[it] * GBS + c4_[it]) = bv;
        }
    }
    __syncthreads();

    int buf = 0;
    for (int k0 = 0; k0 < D; k0 += GBK) {
        const int kn = k0 + GBK;
        float4 na[2], nb[2];
        if (kn < D) {
#pragma unroll
            for (int it = 0; it < 2; it++) {
                na[it] = make_float4(0.f, 0.f, 0.f, 0.f);
                if (m0 + row_[it] < M)
                    na[it] = *(const float4*)(A + (size_t)(m0 + row_[it]) * D + kn + c4_[it]);
                nb[it] = *(const float4*)(W + (size_t)(n0 + row_[it]) * D + kn + c4_[it]);
            }
        }

        const float* As = s.As[buf];
        const float* Bs = s.Bs[buf];
#pragma unroll
        for (int ss = 0; ss < 2; ss++) {
            const int kk = ss * 8;
            unsigned a[4][4];
#pragma unroll
            for (int i = 0; i < 4; i++) {
                int r = wm + i * 16 + g;
                a[i][0] = __float_as_uint(As[r * GAS + kk + t]);
                a[i][1] = __float_as_uint(As[(r + 8) * GAS + kk + t]);
                a[i][2] = __float_as_uint(As[r * GAS + kk + t + 4]);
                a[i][3] = __float_as_uint(As[(r + 8) * GAS + kk + t + 4]);
            }
#pragma unroll
            for (int j = 0; j < 4; j++) {
                int n = wn + j * 8 + g;
                unsigned b0 = __float_as_uint(Bs[n * GBS + kk + t]);
                unsigned b1 = __float_as_uint(Bs[n * GBS + kk + t + 4]);
#pragma unroll
                for (int i = 0; i < 4; i++)
                    mma_tf32(acc[i][j], a[i][0], a[i][1], a[i][2], a[i][3], b0, b1);
            }
        }

        if (kn < D) {
            const int nb_ = buf ^ 1;
#pragma unroll
            for (int it = 0; it < 2; it++) {
                float4 av = na[it], bv = nb[it];
                av.x = tf32r(av.x); av.y = tf32r(av.y);
                av.z = tf32r(av.z); av.w = tf32r(av.w);
                bv.x = tf32r(bv.x); bv.y = tf32r(bv.y);
                bv.z = tf32r(bv.z); bv.w = tf32r(bv.w);
                *(float4*)(s.As[nb_] + row_[it] * GAS + c4_[it]) = av;
                *(float4*)(s.Bs[nb_] + row_[it] * GBS + c4_[it]) = bv;
            }
        }
        __syncthreads();
        buf ^= 1;
    }

    // epilogue
#pragma unroll
    for (int j = 0; j < 4; j++) {
        int c0 = n0 + wn + j * 8 + t * 2;
        float b0v = bias ? bias[c0] : 0.f;
        float b1v = bias ? bias[c0 + 1] : 0.f;
#pragma unroll
        for (int i = 0; i < 4; i++) {
            int r0 = m0 + wm + i * 16 + g;
            int r1 = r0 + 8;
            if (r0 < M) {
                float2 p;
                p.x = (acc[i][j][0] + b0v) * scale;
                p.y = (acc[i][j][1] + b1v) * scale;
                *(float2*)(C + (size_t)r0 * D + c0) = p;
            }
            if (r1 < M) {
                float2 p;
                p.x = (acc[i][j][2] + b0v) * scale;
                p.y = (acc[i][j][3] + b1v) * scale;
                *(float2*)(C + (size_t)r1 * D + c0) = p;
            }
        }
    }
}

// Fused QKV: grid (6, 34, 3). y==33 is the det tile (rows 4201..4300).
__global__ void __launch_bounds__(256, 2) qkv_gemm(
    const float* __restrict__ x,
    const float* __restrict__ wq_p, const float* __restrict__ wq_d,
    const float* __restrict__ wk_p, const float* __restrict__ wk_d,
    const float* __restrict__ wv_p, const float* __restrict__ wv_d,
    const float* __restrict__ bq_p, const float* __restrict__ bq_d,
    const float* __restrict__ bv_p, const float* __restrict__ bv_d,
    float* __restrict__ q, float* __restrict__ k, float* __restrict__ v)
{
    __shared__ GemmSmem s;
    const bool det = (blockIdx.y == gridDim.y - 1);
    const int m0 = det ? NP : blockIdx.y * 128;
    const int M  = det ? N_TOK : NP;
    const int z = blockIdx.z;

    const float* W;
    const float* bias;
    float* C;
    float scale = 1.f;
    if (z == 0) {
        W = det ? wq_d : wq_p; bias = det ? bq_d : bq_p; C = q; scale = QSCALE;
    } else if (z == 1) {
        W = det ? wk_d : wk_p; bias = nullptr; C = k;
    } else {
        W = det ? wv_d : wv_p; bias = det ? bv_d : bv_p; C = v;
    }
    gemm_tile_body(x, W, bias, C, m0, blockIdx.x * 128, M, scale, s);
}

// Fused out-projection: grid (6, 34). y==33 is the det tile.
__global__ void __launch_bounds__(256, 2) out_gemm(
    const float* __restrict__ A,
    const float* __restrict__ wo_p, const float* __restrict__ wo_d,
    const float* __restrict__ bo_p, const float* __restrict__ bo_d,
    float* __restrict__ C)
{
    __shared__ GemmSmem s;
    const bool det = (blockIdx.y == gridDim.y - 1);
    const int m0 = det ? NP : blockIdx.y * 128;
    const int M  = det ? N_TOK : NP;
    gemm_tile_body(A, det ? wo_d : wo_p, det ? bo_d : bo_p, C,
                   m0, blockIdx.x * 128, M, 1.f, s);
}

// ---------------------------------------------------------------------------
// Tensor-core flash attention (tf32).
// Block: 256 thr (8 warps), 256 queries x one head. Warp owns 32 q rows
// (2 m16 subtiles) -> K/V smem reads amortized over 2x more queries.
// K tile 64 keys. Online softmax in registers on the mma C-fragment layout.
// P (C-layout) -> A-layout via warp shuffles, no smem round trip.
// ---------------------------------------------------------------------------
#define QTILE 256
#define QS_S 68
#define KS_S 68
#define VS_S 72
#define ATT_SMEM ((QTILE * QS_S + 64 * KS_S + 64 * VS_S) * 4)

__global__ void __launch_bounds__(256) attn_tc(
    const float* __restrict__ q, const float* __restrict__ k,
    const float* __restrict__ v, float* __restrict__ o)
{
    extern __shared__ float sm[];
    float* Qs = sm;                                 // [QTILE][QS_S]
    float* Ks = sm + QTILE * QS_S;                  // [64][KS_S]
    float* Vs = sm + QTILE * QS_S + 64 * KS_S;      // [64][VS_S]

    const int h = blockIdx.y;
    const int q0 = blockIdx.x * QTILE;
    const int tid = threadIdx.x;
    const int w = tid >> 5;
    const int l = tid & 31;
    const int g = l >> 2;
    const int t = l & 3;
    // subtile u (0,1): c-frag rows ru = w*32 + u*16 + g and ru+8

    // Load Q tile (tf32-rounded, zero-padded)
#pragma unroll
    for (int it = 0; it < QTILE / 16; it++) {
        int slot = tid + 256 * it;      // QTILE*16 float4 slots
        int row = slot >> 4;
        int c4 = (slot & 15) * 4;
        float4 val = make_float4(0.f, 0.f, 0.f, 0.f);
        if (q0 + row < N_TOK)
            val = *(const float4*)(q + (size_t)(q0 + row) * D + h * HD + c4);
        val.x = tf32r(val.x); val.y = tf32r(val.y);
        val.z = tf32r(val.z); val.w = tf32r(val.w);
        *(float4*)(Qs + row * QS_S + c4) = val;
    }
    __syncthreads();

    float mr0[2] = { -1e30f, -1e30f }, mr1[2] = { -1e30f, -1e30f };
    float lr0[2] = { 0.f, 0.f }, lr1[2] = { 0.f, 0.f };
    float oacc[2][8][4];
#pragma unroll
    for (int u = 0; u < 2; u++)
#pragma unroll
        for (int n = 0; n < 8; n++)
#pragma unroll
            for (int r = 0; r < 4; r++) oacc[u][n][r] = 0.f;

    const int srcA = (l & ~3) | (t >> 1);
    const int srcB = srcA + 2;
    const bool odd = (t & 1);

    for (int t0 = 0; t0 < N_TOK; t0 += 64) {
        const int cnt = min(64, N_TOK - t0);

        // Fill K and V tiles (zero-padded)
#pragma unroll
        for (int it = 0; it < 4; it++) {
            int slot = tid + 256 * it;   // 1024 float4 slots
            int row = slot >> 4;
            int c4 = (slot & 15) * 4;
            float4 kv = make_float4(0.f, 0.f, 0.f, 0.f);
            float4 vv = make_float4(0.f, 0.f, 0.f, 0.f);
            if (row < cnt) {
                kv = *(const float4*)(k + (size_t)(t0 + row) * D + h * HD + c4);
                vv = *(const float4*)(v + (size_t)(t0 + row) * D + h * HD + c4);
            }
            kv.x = tf32r(kv.x); kv.y = tf32r(kv.y);
            kv.z = tf32r(kv.z); kv.w = tf32r(kv.w);
            vv.x = tf32r(vv.x); vv.y = tf32r(vv.y);
            vv.z = tf32r(vv.z); vv.w = tf32r(vv.w);
            *(float4*)(Ks + row * KS_S + c4) = kv;
            *(float4*)(Vs + row * VS_S + c4) = vv;
        }
        __syncthreads();

        // S = Q @ K^T  (both q-subtiles share K b-frags)
        float sc[2][8][4];
#pragma unroll
        for (int u = 0; u < 2; u++)
#pragma unroll
            for (int n = 0; n < 8; n++)
#pragma unroll
                for (int r = 0; r < 4; r++) sc[u][n][r] = 0.f;

#pragma unroll
        for (int s = 0; s < 8; s++) {
            unsigned a[2][4];
#pragma unroll
            for (int u = 0; u < 2; u++) {
                int ru = w * 32 + u * 16 + g;
                a[u][0] = __float_as_uint(Qs[ru * QS_S + s * 8 + t]);
                a[u][1] = __float_as_uint(Qs[(ru + 8) * QS_S + s * 8 + t]);
                a[u][2] = __float_as_uint(Qs[ru * QS_S + s * 8 + t + 4]);
                a[u][3] = __float_as_uint(Qs[(ru + 8) * QS_S + s * 8 + t + 4]);
            }
#pragma unroll
            for (int n = 0; n < 8; n++) {
                unsigned b0 = __float_as_uint(Ks[(n * 8 + g) * KS_S + s * 8 + t]);
                unsigned b1 = __float_as_uint(Ks[(n * 8 + g) * KS_S + s * 8 + t + 4]);
                mma_tf32(sc[0][n], a[0][0], a[0][1], a[0][2], a[0][3], b0, b1);
                mma_tf32(sc[1][n], a[1][0], a[1][1], a[1][2], a[1][3], b0, b1);
            }
        }

        // Mask padded keys (last tile only)
        if (cnt < 64) {
#pragma unroll
            for (int u = 0; u < 2; u++)
#pragma unroll
                for (int n = 0; n < 8; n++) {
                    int j0 = n * 8 + t * 2;
                    if (j0 >= cnt)     { sc[u][n][0] = -1e30f; sc[u][n][2] = -1e30f; }
                    if (j0 + 1 >= cnt) { sc[u][n][1] = -1e30f; sc[u][n][3] = -1e30f; }
                }
        }

        // Online softmax per subtile
        float esc0[2], esc1[2];
#pragma unroll
        for (int u = 0; u < 2; u++) {
            float mx0 = -1e30f, mx1 = -1e30f;
#pragma unroll
            for (int n = 0; n < 8; n++) {
                mx0 = fmaxf(mx0, fmaxf(sc[u][n][0], sc[u][n][1]));
                mx1 = fmaxf(mx1, fmaxf(sc[u][n][2], sc[u][n][3]));
            }
            mx0 = fmaxf(mx0, __shfl_xor_sync(0xffffffffu, mx0, 1));
            mx0 = fmaxf(mx0, __shfl_xor_sync(0xffffffffu, mx0, 2));
            mx1 = fmaxf(mx1, __shfl_xor_sync(0xffffffffu, mx1, 1));
            mx1 = fmaxf(mx1, __shfl_xor_sync(0xffffffffu, mx1, 2));
            float nm0 = fmaxf(mr0[u], mx0), nm1 = fmaxf(mr1[u], mx1);
            esc0[u] = __expf(mr0[u] - nm0);
            esc1[u] = __expf(mr1[u] - nm1);
            mr0[u] = nm0; mr1[u] = nm1;

            float sum0 = 0.f, sum1 = 0.f;
#pragma unroll
            for (int n = 0; n < 8; n++) {
                sc[u][n][0] = __expf(sc[u][n][0] - nm0);
                sc[u][n][1] = __expf(sc[u][n][1] - nm0);
                sc[u][n][2] = __expf(sc[u][n][2] - nm1);
                sc[u][n][3] = __expf(sc[u][n][3] - nm1);
                sum0 += sc[u][n][0] + sc[u][n][1];
                sum1 += sc[u][n][2] + sc[u][n][3];
            }
            sum0 += __shfl_xor_sync(0xffffffffu, sum0, 1);
            sum0 += __shfl_xor_sync(0xffffffffu, sum0, 2);
            sum1 += __shfl_xor_sync(0xffffffffu, sum1, 1);
            sum1 += __shfl_xor_sync(0xffffffffu, sum1, 2);
            lr0[u] = lr0[u] * esc0[u] + sum0;
            lr1[u] = lr1[u] * esc1[u] + sum1;
        }

        if (__any_sync(0xffffffffu,
                (esc0[0] != 1.f) || (esc1[0] != 1.f) ||
                (esc0[1] != 1.f) || (esc1[1] != 1.f))) {
#pragma unroll
            for (int u = 0; u < 2; u++)
#pragma unroll
                for (int n = 0; n < 8; n++) {
                    oacc[u][n][0] *= esc0[u]; oacc[u][n][1] *= esc0[u];
                    oacc[u][n][2] *= esc1[u]; oacc[u][n][3] *= esc1[u];
                }
        }

        // O += P @ V.  V b-frags shared across subtiles.
#pragma unroll
        for (int s = 0; s < 8; s++) {
            unsigned a[2][4];
#pragma unroll
            for (int u = 0; u < 2; u++) {
                float v00 = __shfl_sync(0xffffffffu, sc[u][s][0], srcA);
                float v01 = __shfl_sync(0xffffffffu, sc[u][s][1], srcA);
                float v10 = __shfl_sync(0xffffffffu, sc[u][s][2], srcA);
                float v11 = __shfl_sync(0xffffffffu, sc[u][s][3], srcA);
                float w00 = __shfl_sync(0xffffffffu, sc[u][s][0], srcB);
                float w01 = __shfl_sync(0xffffffffu, sc[u][s][1], srcB);
                float w10 = __shfl_sync(0xffffffffu, sc[u][s][2], srcB);
                float w11 = __shfl_sync(0xffffffffu, sc[u][s][3], srcB);
                a[u][0] = f2tf32(odd ? v01 : v00);
                a[u][1] = f2tf32(odd ? v11 : v10);
                a[u][2] = f2tf32(odd ? w01 : w00);
                a[u][3] = f2tf32(odd ? w11 : w10);
            }
#pragma unroll
            for (int n = 0; n < 8; n++) {
                unsigned b0 = __float_as_uint(Vs[(s * 8 + t) * VS_S + n * 8 + g]);
                unsigned b1 = __float_as_uint(Vs[(s * 8 + t + 4) * VS_S + n * 8 + g]);
                mma_tf32(oacc[0][n], a[0][0], a[0][1], a[0][2], a[0][3], b0, b1);
                mma_tf32(oacc[1][n], a[1][0], a[1][1], a[1][2], a[1][3], b0, b1);
            }
        }
        __syncthreads();
    }

    // Epilogue
#pragma unroll
    for (int u = 0; u < 2; u++) {
        float i0 = 1.f / lr0[u], i1 = 1.f / lr1[u];
        int gr0 = q0 + w * 32 + u * 16 + g;
        int gr1 = gr0 + 8;
#pragma unroll
        for (int n = 0; n < 8; n++) {
            int c = h * HD + n * 8 + t * 2;
            if (gr0 < N_TOK) {
                float2 p;
                p.x = oacc[u][n][0] * i0; p.y = oacc[u][n][1] * i0;
                *(float2*)(o + (size_t)gr0 * D + c) = p;
            }
            if (gr1 < N_TOK) {
                float2 p;
                p.x = oacc[u][n][2] * i1; p.y = oacc[u][n][3] * i1;
                *(float2*)(o + (size_t)gr1 * D + c) = p;
            }
        }
    }
}

// ---------------------------------------------------------------------------
// LayerNorm (in place): one block per token row.
// ---------------------------------------------------------------------------
__global__ void __launch_bounds__(256) ln_kernel(
    float* __restrict__ o, const float* __restrict__ g, const float* __restrict__ b)
{
    const int row = blockIdx.x;
    float* p = o + (size_t)row * D;
    const int t = threadIdx.x;
    float x0 = p[t], x1 = p[t + 256], x2 = p[t + 512];
    float s = x0 + x1 + x2;
    float sq = x0 * x0 + x1 * x1 + x2 * x2;

    __shared__ float red[64];
#pragma unroll
    for (int off = 16; off > 0; off >>= 1) {
        s  += __shfl_down_sync(0xffffffffu, s, off);
        sq += __shfl_down_sync(0xffffffffu, sq, off);
    }
    int wid = t >> 5, lid = t & 31;
    if (lid == 0) { red[wid] = s; red[wid + 32] = sq; }
    __syncthreads();
    __shared__ float mu_s, rstd_s;
    if (t == 0) {
        float S = 0.f, SQ = 0.f;
#pragma unroll
        for (int i = 0; i < 8; i++) { S += red[i]; SQ += red[i + 32]; }
        float mu = S * (1.f / D);
        float var = SQ * (1.f / D) - mu * mu;
        mu_s = mu;
        rstd_s = rsqrtf(var + 1e-5f);
    }
    __syncthreads();
    float mu = mu_s, r = rstd_s;
    p[t]       = (x0 - mu) * r * g[t]       + b[t];
    p[t + 256] = (x1 - mu) * r * g[t + 256] + b[t + 256];
    p[t + 512] = (x2 - mu) * r * g[t + 512] + b[t + 512];
}

// ---------------------------------------------------------------------------
extern "C" void kernel_launch(void* const* d_in, const int* in_sizes, int n_in,
                              void* d_out, int out_size)
{
    const float* x    = (const float*)d_in[0];
    const float* wq_p = (const float*)d_in[1];
    const float* wk_p = (const float*)d_in[2];
    const float* wv_p = (const float*)d_in[3];
    const float* wq_d = (const float*)d_in[4];
    const float* wk_d = (const float*)d_in[5];
    const float* wv_d = (const float*)d_in[6];
    const float* bq_p = (const float*)d_in[7];
    const float* bv_p = (const float*)d_in[8];
    const float* bq_d = (const float*)d_in[9];
    const float* bv_d = (const float*)d_in[10];
    const float* ln_g = (const float*)d_in[11];
    const float* ln_b = (const float*)d_in[12];
    const float* wo_p = (const float*)d_in[13];
    const float* bo_p = (const float*)d_in[14];
    const float* wo_d = (const float*)d_in[15];
    const float* bo_d = (const float*)d_in[16];
    float* out = (float*)d_out;

    float *q, *k, *v, *o;
    cudaGetSymbolAddress((void**)&q, g_q);
    cudaGetSymbolAddress((void**)&k, g_k);
    cudaGetSymbolAddress((void**)&v, g_v);
    cudaGetSymbolAddress((void**)&o, g_o);

    cudaFuncSetAttribute(attn_tc, cudaFuncAttributeMaxDynamicSharedMemorySize, ATT_SMEM);

    // Fused QKV projections: 6 x 34 x 3 = 612 blocks, one launch.
    dim3 gq(D / 128, 34, 3);
    qkv_gemm<<<gq, 256>>>(x, wq_p, wq_d, wk_p, wk_d, wv_p, wv_d,
                          bq_p, bq_d, bv_p, bv_d, q, k, v);

    // Attention (tensor-core flash, 256-query tiles)
    dim3 ga((N_TOK + QTILE - 1) / QTILE, H);   // (17, 12)
    attn_tc<<<ga, 256, ATT_SMEM>>>(q, k, v, o);

    // LayerNorm (in place on o)
    ln_kernel<<<N_TOK, 256>>>(o, ln_g, ln_b);

    // Output projection (patch + det fused)
    dim3 go(D / 128, 34);
    out_gemm<<<go, 256>>>(o, wo_p, wo_d, bo_p, bo_d, out);
}

// round 7
// speedup vs baseline: 1.1415x; 1.1415x over previous
#include <cuda_runtime.h>
#include <math.h>

#define N_TOK 4301
#define NP    4201
#define ND    100
#define D     768
#define H     12
#define HD    64
#define QSCALE 0.125f

// Scratch (allocation-free rule: __device__ globals)
__device__ float g_q[(size_t)N_TOK * D];
__device__ float g_k[(size_t)N_TOK * D];
__device__ float g_v[(size_t)N_TOK * D];
__device__ float g_o[(size_t)N_TOK * D];

// ---------------------------------------------------------------------------
// tf32 + cp.async helpers
// ---------------------------------------------------------------------------
__device__ __forceinline__ unsigned f2tf32(float x) {
    unsigned u;
    asm("cvt.rna.tf32.f32 %0, %1;" : "=r"(u) : "f"(x));
    return u;
}
__device__ __forceinline__ float tf32r(float x) {
    return __uint_as_float(f2tf32(x));
}
__device__ __forceinline__ void mma_tf32(float* c,
    unsigned a0, unsigned a1, unsigned a2, unsigned a3,
    unsigned b0, unsigned b1)
{
    asm volatile(
        "mma.sync.aligned.m16n8k8.row.col.f32.tf32.tf32.f32 "
        "{%0,%1,%2,%3}, {%4,%5,%6,%7}, {%8,%9}, {%0,%1,%2,%3};"
        : "+f"(c[0]), "+f"(c[1]), "+f"(c[2]), "+f"(c[3])
        : "r"(a0), "r"(a1), "r"(a2), "r"(a3), "r"(b0), "r"(b1));
}
__device__ __forceinline__ void cp_async16(unsigned dst, const void* src, int srcsize) {
    asm volatile("cp.async.cg.shared.global [%0], [%1], 16, %2;"
                 :: "r"(dst), "l"(src), "r"(srcsize));
}
__device__ __forceinline__ void cp_commit() {
    asm volatile("cp.async.commit_group;");
}

// ---------------------------------------------------------------------------
// GEMM tile body: C[tile] = (A @ W^T + bias) * scale  [optionally tf32-rounded]
// Block 256 thr (8 warps, 2m x 4n), tile 128x128, BK=16.
// Ping-pong double-buffered smem: ONE barrier per K-iter, LDG overlapped.
// ---------------------------------------------------------------------------
#define GBK 16
#define GAS 20   // As stride (floats)
#define GBS 20   // Bs stride

struct GemmSmem {
    float As[2][128 * GAS];
    float Bs[2][128 * GBS];
};

__device__ __forceinline__ void gemm_tile_body(
    const float* __restrict__ A,
    const float* __restrict__ W,
    const float* __restrict__ bias,
    float* __restrict__ C,
    int m0, int n0, int M, float scale, bool rnd_out,
    GemmSmem& s)
{
    const int tid = threadIdx.x;
    const int w = tid >> 5;
    const int l = tid & 31;
    const int g = l >> 2;
    const int t = l & 3;
    const int wm = (w >> 2) * 64;
    const int wn = (w & 3) * 32;

    int row_[2], c4_[2];
#pragma unroll
    for (int it = 0; it < 2; it++) {
        int slot = tid + 256 * it;
        row_[it] = slot >> 2;
        c4_[it]  = (slot & 3) * 4;
    }

    float acc[4][4][4];
#pragma unroll
    for (int i = 0; i < 4; i++)
#pragma unroll
        for (int j = 0; j < 4; j++)
#pragma unroll
            for (int r = 0; r < 4; r++) acc[i][j][r] = 0.f;

    // prologue: load + store k0 = 0 into buffer 0
    {
#pragma unroll
        for (int it = 0; it < 2; it++) {
            float4 av = make_float4(0.f, 0.f, 0.f, 0.f);
            if (m0 + row_[it] < M)
                av = *(const float4*)(A + (size_t)(m0 + row_[it]) * D + c4_[it]);
            float4 bv = *(const float4*)(W + (size_t)(n0 + row_[it]) * D + c4_[it]);
            av.x = tf32r(av.x); av.y = tf32r(av.y);
            av.z = tf32r(av.z); av.w = tf32r(av.w);
            bv.x = tf32r(bv.x); bv.y = tf32r(bv.y);
            bv.z = tf32r(bv.z); bv.w = tf32r(bv.w);
            *(float4*)(s.As[0] + row_[it] * GAS + c4_[it]) = av;
            *(float4*)(s.Bs[0] + row_[it] * GBS + c4_[it]) = bv;
        }
    }
    __syncthreads();

    int buf = 0;
    for (int k0 = 0; k0 < D; k0 += GBK) {
        const int kn = k0 + GBK;
        float4 na[2], nb[2];
        if (kn < D) {
#pragma unroll
            for (int it = 0; it < 2; it++) {
                na[it] = make_float4(0.f, 0.f, 0.f, 0.f);
                if (m0 + row_[it] < M)
                    na[it] = *(const float4*)(A + (size_t)(m0 + row_[it]) * D + kn + c4_[it]);
                nb[it] = *(const float4*)(W + (size_t)(n0 + row_[it]) * D + kn + c4_[it]);
            }
        }

        const float* As = s.As[buf];
        const float* Bs = s.Bs[buf];
#pragma unroll
        for (int ss = 0; ss < 2; ss++) {
            const int kk = ss * 8;
            unsigned a[4][4];
#pragma unroll
            for (int i = 0; i < 4; i++) {
                int r = wm + i * 16 + g;
                a[i][0] = __float_as_uint(As[r * GAS + kk + t]);
                a[i][1] = __float_as_uint(As[(r + 8) * GAS + kk + t]);
                a[i][2] = __float_as_uint(As[r * GAS + kk + t + 4]);
                a[i][3] = __float_as_uint(As[(r + 8) * GAS + kk + t + 4]);
            }
#pragma unroll
            for (int j = 0; j < 4; j++) {
                int n = wn + j * 8 + g;
                unsigned b0 = __float_as_uint(Bs[n * GBS + kk + t]);
                unsigned b1 = __float_as_uint(Bs[n * GBS + kk + t + 4]);
#pragma unroll
                for (int i = 0; i < 4; i++)
                    mma_tf32(acc[i][j], a[i][0], a[i][1], a[i][2], a[i][3], b0, b1);
            }
        }

        if (kn < D) {
            const int nb_ = buf ^ 1;
#pragma unroll
            for (int it = 0; it < 2; it++) {
                float4 av = na[it], bv = nb[it];
                av.x = tf32r(av.x); av.y = tf32r(av.y);
                av.z = tf32r(av.z); av.w = tf32r(av.w);
                bv.x = tf32r(bv.x); bv.y = tf32r(bv.y);
                bv.z = tf32r(bv.z); bv.w = tf32r(bv.w);
                *(float4*)(s.As[nb_] + row_[it] * GAS + c4_[it]) = av;
                *(float4*)(s.Bs[nb_] + row_[it] * GBS + c4_[it]) = bv;
            }
        }
        __syncthreads();
        buf ^= 1;
    }

    // epilogue (optionally tf32-round outputs so attention can cp.async them raw)
#pragma unroll
    for (int j = 0; j < 4; j++) {
        int c0 = n0 + wn + j * 8 + t * 2;
        float b0v = bias ? bias[c0] : 0.f;
        float b1v = bias ? bias[c0 + 1] : 0.f;
#pragma unroll
        for (int i = 0; i < 4; i++) {
            int r0 = m0 + wm + i * 16 + g;
            int r1 = r0 + 8;
            if (r0 < M) {
                float2 p;
                p.x = (acc[i][j][0] + b0v) * scale;
                p.y = (acc[i][j][1] + b1v) * scale;
                if (rnd_out) { p.x = tf32r(p.x); p.y = tf32r(p.y); }
                *(float2*)(C + (size_t)r0 * D + c0) = p;
            }
            if (r1 < M) {
                float2 p;
                p.x = (acc[i][j][2] + b0v) * scale;
                p.y = (acc[i][j][3] + b1v) * scale;
                if (rnd_out) { p.x = tf32r(p.x); p.y = tf32r(p.y); }
                *(float2*)(C + (size_t)r1 * D + c0) = p;
            }
        }
    }
}

// Fused QKV: grid (6, 34, 3). y==33 is the det tile (rows 4201..4300).
__global__ void __launch_bounds__(256, 2) qkv_gemm(
    const float* __restrict__ x,
    const float* __restrict__ wq_p, const float* __restrict__ wq_d,
    const float* __restrict__ wk_p, const float* __restrict__ wk_d,
    const float* __restrict__ wv_p, const float* __restrict__ wv_d,
    const float* __restrict__ bq_p, const float* __restrict__ bq_d,
    const float* __restrict__ bv_p, const float* __restrict__ bv_d,
    float* __restrict__ q, float* __restrict__ k, float* __restrict__ v)
{
    __shared__ GemmSmem s;
    const bool det = (blockIdx.y == gridDim.y - 1);
    const int m0 = det ? NP : blockIdx.y * 128;
    const int M  = det ? N_TOK : NP;
    const int z = blockIdx.z;

    const float* W;
    const float* bias;
    float* C;
    float scale = 1.f;
    if (z == 0) {
        W = det ? wq_d : wq_p; bias = det ? bq_d : bq_p; C = q; scale = QSCALE;
    } else if (z == 1) {
        W = det ? wk_d : wk_p; bias = nullptr; C = k;
    } else {
        W = det ? wv_d : wv_p; bias = det ? bv_d : bv_p; C = v;
    }
    // outputs tf32-rounded: attention consumes them raw via cp.async
    gemm_tile_body(x, W, bias, C, m0, blockIdx.x * 128, M, scale, true, s);
}

// Fused out-projection: grid (6, 34). y==33 is the det tile.
__global__ void __launch_bounds__(256, 2) out_gemm(
    const float* __restrict__ A,
    const float* __restrict__ wo_p, const float* __restrict__ wo_d,
    const float* __restrict__ bo_p, const float* __restrict__ bo_d,
    float* __restrict__ C)
{
    __shared__ GemmSmem s;
    const bool det = (blockIdx.y == gridDim.y - 1);
    const int m0 = det ? NP : blockIdx.y * 128;
    const int M  = det ? N_TOK : NP;
    gemm_tile_body(A, det ? wo_d : wo_p, det ? bo_d : bo_p, C,
                   m0, blockIdx.x * 128, M, 1.f, false, s);
}

// ---------------------------------------------------------------------------
// Tensor-core flash attention (tf32), cp.async double-buffered K/V tiles.
// Block: 256 thr (8 warps), 128 queries x one head. Warp owns 16 q rows.
// Inputs q/k/v are pre-rounded to tf32 by the QKV GEMM epilogue, so tiles
// stream straight into smem with LDGSTS (no register staging, no cvt).
// ---------------------------------------------------------------------------
#define QS_S 68
#define KS_S 68
#define VS_S 72
#define NKT ((N_TOK + 63) / 64)   // 68 key tiles
#define ATT_SMEM ((128 * QS_S + 2 * 64 * KS_S + 2 * 64 * VS_S) * 4)

__global__ void __launch_bounds__(256) attn_tc(
    const float* __restrict__ q, const float* __restrict__ k,
    const float* __restrict__ v, float* __restrict__ o)
{
    extern __shared__ float sm[];
    float* Qs = sm;                                   // [128][QS_S]
    float* Ks0 = sm + 128 * QS_S;                     // [2][64][KS_S]
    float* Vs0 = Ks0 + 2 * 64 * KS_S;                 // [2][64][VS_S]

    const int h = blockIdx.y;
    const int q0 = blockIdx.x * 128;
    const int tid = threadIdx.x;
    const int w = tid >> 5;
    const int l = tid & 31;
    const int g = l >> 2;
    const int t = l & 3;
    const int r0 = w * 16 + g;

    // per-thread K/V chunk coords (4 chunks each of 16B)
    int kr_[4], kc_[4];
#pragma unroll
    for (int it = 0; it < 4; it++) {
        int slot = tid + 256 * it;      // 1024 float4 slots
        kr_[it] = slot >> 4;            // 0..63
        kc_[it] = (slot & 15) * 4;
    }
    unsigned ks_u32 = (unsigned)__cvta_generic_to_shared(Ks0);
    unsigned vs_u32 = (unsigned)__cvta_generic_to_shared(Vs0);

    // issue K/V prefetch for tile 0 into buffer 0
    {
        const int cnt = 64;   // tile 0 is full
#pragma unroll
        for (int it = 0; it < 4; it++) {
            int row = kr_[it], c4 = kc_[it];
            int ok = (row < cnt) ? 16 : 0;
            cp_async16(ks_u32 + (row * KS_S + c4) * 4,
                       k + (size_t)row * D + h * HD + c4, ok);
            cp_async16(vs_u32 + (row * VS_S + c4) * 4,
                       v + (size_t)row * D + h * HD + c4, ok);
        }
        cp_commit();
    }

    // Load Q tile (pre-rounded, zero-padded)
#pragma unroll
    for (int it = 0; it < 8; it++) {
        int slot = tid + 256 * it;      // 2048 float4 slots
        int row = slot >> 4;
        int c4 = (slot & 15) * 4;
        float4 val = make_float4(0.f, 0.f, 0.f, 0.f);
        if (q0 + row < N_TOK)
            val = *(const float4*)(q + (size_t)(q0 + row) * D + h * HD + c4);
        *(float4*)(Qs + row * QS_S + c4) = val;
    }

    float m0 = -1e30f, m1 = -1e30f, l0 = 0.f, l1 = 0.f;
    float oacc[8][4];
#pragma unroll
    for (int n = 0; n < 8; n++)
#pragma unroll
        for (int r = 0; r < 4; r++) oacc[n][r] = 0.f;

    const int srcA = (l & ~3) | (t >> 1);
    const int srcB = srcA + 2;
    const bool odd = (t & 1);

    int buf = 0;
    for (int ti = 0; ti < NKT; ti++) {
        const int t0 = ti * 64;
        const int cnt = min(64, N_TOK - t0);

        // prefetch next tile into buf^1
        if (ti + 1 < NKT) {
            const int nt0 = t0 + 64;
            const int ncnt = min(64, N_TOK - nt0);
            const unsigned kb = ks_u32 + (buf ^ 1) * 64 * KS_S * 4;
            const unsigned vb = vs_u32 + (buf ^ 1) * 64 * VS_S * 4;
#pragma unroll
            for (int it = 0; it < 4; it++) {
                int row = kr_[it], c4 = kc_[it];
                int ok = (row < ncnt) ? 16 : 0;
                size_t off = (size_t)(nt0 + (ok ? row : 0)) * D + h * HD + c4;
                cp_async16(kb + (row * KS_S + c4) * 4, k + off, ok);
                cp_async16(vb + (row * VS_S + c4) * 4, v + off, ok);
            }
            cp_commit();
            asm volatile("cp.async.wait_group 1;");
        } else {
            asm volatile("cp.async.wait_group 0;");
        }
        __syncthreads();

        const float* Ks = Ks0 + buf * 64 * KS_S;
        const float* Vs = Vs0 + buf * 64 * VS_S;

        // S = Q @ K^T
        float sc[8][4];
#pragma unroll
        for (int n = 0; n < 8; n++)
#pragma unroll
            for (int r = 0; r < 4; r++) sc[n][r] = 0.f;

#pragma unroll
        for (int s = 0; s < 8; s++) {
            unsigned a0 = __float_as_uint(Qs[r0 * QS_S + s * 8 + t]);
            unsigned a1 = __float_as_uint(Qs[(r0 + 8) * QS_S + s * 8 + t]);
            unsigned a2 = __float_as_uint(Qs[r0 * QS_S + s * 8 + t + 4]);
            unsigned a3 = __float_as_uint(Qs[(r0 + 8) * QS_S + s * 8 + t + 4]);
#pragma unroll
            for (int n = 0; n < 8; n++) {
                unsigned b0 = __float_as_uint(Ks[(n * 8 + g) * KS_S + s * 8 + t]);
                unsigned b1 = __float_as_uint(Ks[(n * 8 + g) * KS_S + s * 8 + t + 4]);
                mma_tf32(sc[n], a0, a1, a2, a3, b0, b1);
            }
        }

        // Mask padded keys (cp.async zero-fills them; scores there are 0)
        if (cnt < 64) {
#pragma unroll
            for (int n = 0; n < 8; n++) {
                int j0 = n * 8 + t * 2;
                if (j0 >= cnt)     { sc[n][0] = -1e30f; sc[n][2] = -1e30f; }
                if (j0 + 1 >= cnt) { sc[n][1] = -1e30f; sc[n][3] = -1e30f; }
            }
        }

        // Online softmax (rows r0, r0+8)
        float mx0 = -1e30f, mx1 = -1e30f;
#pragma unroll
        for (int n = 0; n < 8; n++) {
            mx0 = fmaxf(mx0, fmaxf(sc[n][0], sc[n][1]));
            mx1 = fmaxf(mx1, fmaxf(sc[n][2], sc[n][3]));
        }
        mx0 = fmaxf(mx0, __shfl_xor_sync(0xffffffffu, mx0, 1));
        mx0 = fmaxf(mx0, __shfl_xor_sync(0xffffffffu, mx0, 2));
        mx1 = fmaxf(mx1, __shfl_xor_sync(0xffffffffu, mx1, 1));
        mx1 = fmaxf(mx1, __shfl_xor_sync(0xffffffffu, mx1, 2));
        float nm0 = fmaxf(m0, mx0), nm1 = fmaxf(m1, mx1);
        float esc0 = __expf(m0 - nm0), esc1 = __expf(m1 - nm1);
        m0 = nm0; m1 = nm1;

        float sum0 = 0.f, sum1 = 0.f;
#pragma unroll
        for (int n = 0; n < 8; n++) {
            sc[n][0] = __expf(sc[n][0] - m0);
            sc[n][1] = __expf(sc[n][1] - m0);
            sc[n][2] = __expf(sc[n][2] - m1);
            sc[n][3] = __expf(sc[n][3] - m1);
            sum0 += sc[n][0] + sc[n][1];
            sum1 += sc[n][2] + sc[n][3];
        }
        sum0 += __shfl_xor_sync(0xffffffffu, sum0, 1);
        sum0 += __shfl_xor_sync(0xffffffffu, sum0, 2);
        sum1 += __shfl_xor_sync(0xffffffffu, sum1, 1);
        sum1 += __shfl_xor_sync(0xffffffffu, sum1, 2);
        l0 = l0 * esc0 + sum0;
        l1 = l1 * esc1 + sum1;

        if (__any_sync(0xffffffffu, (esc0 != 1.f) || (esc1 != 1.f))) {
#pragma unroll
            for (int n = 0; n < 8; n++) {
                oacc[n][0] *= esc0; oacc[n][1] *= esc0;
                oacc[n][2] *= esc1; oacc[n][3] *= esc1;
            }
        }

        // O += P @ V
#pragma unroll
        for (int s = 0; s < 8; s++) {
            float v00 = __shfl_sync(0xffffffffu, sc[s][0], srcA);
            float v01 = __shfl_sync(0xffffffffu, sc[s][1], srcA);
            float v10 = __shfl_sync(0xffffffffu, sc[s][2], srcA);
            float v11 = __shfl_sync(0xffffffffu, sc[s][3], srcA);
            float w00 = __shfl_sync(0xffffffffu, sc[s][0], srcB);
            float w01 = __shfl_sync(0xffffffffu, sc[s][1], srcB);
            float w10 = __shfl_sync(0xffffffffu, sc[s][2], srcB);
            float w11 = __shfl_sync(0xffffffffu, sc[s][3], srcB);
            unsigned a0 = f2tf32(odd ? v01 : v00);
            unsigned a1 = f2tf32(odd ? v11 : v10);
            unsigned a2 = f2tf32(odd ? w01 : w00);
            unsigned a3 = f2tf32(odd ? w11 : w10);
#pragma unroll
            for (int n = 0; n < 8; n++) {
                unsigned b0 = __float_as_uint(Vs[(s * 8 + t) * VS_S + n * 8 + g]);
                unsigned b1 = __float_as_uint(Vs[(s * 8 + t + 4) * VS_S + n * 8 + g]);
                mma_tf32(oacc[n], a0, a1, a2, a3, b0, b1);
            }
        }
        __syncthreads();
        buf ^= 1;
    }

    // Epilogue
    float i0 = 1.f / l0, i1 = 1.f / l1;
    int gr0 = q0 + r0, gr1 = gr0 + 8;
#pragma unroll
    for (int n = 0; n < 8; n++) {
        int c = h * HD + n * 8 + t * 2;
        if (gr0 < N_TOK) {
            float2 p;
            p.x = oacc[n][0] * i0; p.y = oacc[n][1] * i0;
            *(float2*)(o + (size_t)gr0 * D + c) = p;
        }
        if (gr1 < N_TOK) {
            float2 p;
            p.x = oacc[n][2] * i1; p.y = oacc[n][3] * i1;
            *(float2*)(o + (size_t)gr1 * D + c) = p;
        }
    }
}

// ---------------------------------------------------------------------------
// LayerNorm (in place): one block per token row.
// ---------------------------------------------------------------------------
__global__ void __launch_bounds__(256) ln_kernel(
    float* __restrict__ o, const float* __restrict__ g, const float* __restrict__ b)
{
    const int row = blockIdx.x;
    float* p = o + (size_t)row * D;
    const int t = threadIdx.x;
    float x0 = p[t], x1 = p[t + 256], x2 = p[t + 512];
    float s = x0 + x1 + x2;
    float sq = x0 * x0 + x1 * x1 + x2 * x2;

    __shared__ float red[64];
#pragma unroll
    for (int off = 16; off > 0; off >>= 1) {
        s  += __shfl_down_sync(0xffffffffu, s, off);
        sq += __shfl_down_sync(0xffffffffu, sq, off);
    }
    int wid = t >> 5, lid = t & 31;
    if (lid == 0) { red[wid] = s; red[wid + 32] = sq; }
    __syncthreads();
    __shared__ float mu_s, rstd_s;
    if (t == 0) {
        float S = 0.f, SQ = 0.f;
#pragma unroll
        for (int i = 0; i < 8; i++) { S += red[i]; SQ += red[i + 32]; }
        float mu = S * (1.f / D);
        float var = SQ * (1.f / D) - mu * mu;
        mu_s = mu;
        rstd_s = rsqrtf(var + 1e-5f);
    }
    __syncthreads();
    float mu = mu_s, r = rstd_s;
    p[t]       = (x0 - mu) * r * g[t]       + b[t];
    p[t + 256] = (x1 - mu) * r * g[t + 256] + b[t + 256];
    p[t + 512] = (x2 - mu) * r * g[t + 512] + b[t + 512];
}

// ---------------------------------------------------------------------------
extern "C" void kernel_launch(void* const* d_in, const int* in_sizes, int n_in,
                              void* d_out, int out_size)
{
    const float* x    = (const float*)d_in[0];
    const float* wq_p = (const float*)d_in[1];
    const float* wk_p = (const float*)d_in[2];
    const float* wv_p = (const float*)d_in[3];
    const float* wq_d = (const float*)d_in[4];
    const float* wk_d = (const float*)d_in[5];
    const float* wv_d = (const float*)d_in[6];
    const float* bq_p = (const float*)d_in[7];
    const float* bv_p = (const float*)d_in[8];
    const float* bq_d = (const float*)d_in[9];
    const float* bv_d = (const float*)d_in[10];
    const float* ln_g = (const float*)d_in[11];
    const float* ln_b = (const float*)d_in[12];
    const float* wo_p = (const float*)d_in[13];
    const float* bo_p = (const float*)d_in[14];
    const float* wo_d = (const float*)d_in[15];
    const float* bo_d = (const float*)d_in[16];
    float* out = (float*)d_out;

    float *q, *k, *v, *o;
    cudaGetSymbolAddress((void**)&q, g_q);
    cudaGetSymbolAddress((void**)&k, g_k);
    cudaGetSymbolAddress((void**)&v, g_v);
    cudaGetSymbolAddress((void**)&o, g_o);

    cudaFuncSetAttribute(attn_tc, cudaFuncAttributeMaxDynamicSharedMemorySize, ATT_SMEM);

    // Fused QKV projections: 6 x 34 x 3 = 612 blocks, one launch.
    dim3 gq(D / 128, 34, 3);
    qkv_gemm<<<gq, 256>>>(x, wq_p, wq_d, wk_p, wk_d, wv_p, wv_d,
                          bq_p, bq_d, bv_p, bv_d, q, k, v);

    // Attention (tensor-core flash, cp.async double-buffered K/V)
    dim3 ga((N_TOK + 127) / 128, H);      // (34, 12)
    attn_tc<<<ga, 256, ATT_SMEM>>>(q, k, v, o);

    // LayerNorm (in place on o)
    ln_kernel<<<N_TOK, 256>>>(o, ln_g, ln_b);

    // Output projection (patch + det fused)
    dim3 go(D / 128, 34);
    out_gemm<<<go, 256>>>(o, wo_p, wo_d, bo_p, bo_d, out);
}

// round 8
// speedup vs baseline: 1.1518x; 1.0090x over previous
#include <cuda_runtime.h>
#include <math.h>

#define N_TOK 4301
#define NP    4201
#define ND    100
#define D     768
#define H     12
#define HD    64
#define QSCALE 0.125f

// Scratch (allocation-free rule: __device__ globals)
__device__ float g_q[(size_t)N_TOK * D];
__device__ float g_k[(size_t)N_TOK * D];
__device__ float g_v[(size_t)N_TOK * D];
__device__ float g_o[(size_t)N_TOK * D];

// ---------------------------------------------------------------------------
// tf32 + cp.async helpers
// ---------------------------------------------------------------------------
__device__ __forceinline__ unsigned f2tf32(float x) {
    unsigned u;
    asm("cvt.rna.tf32.f32 %0, %1;" : "=r"(u) : "f"(x));
    return u;
}
__device__ __forceinline__ float tf32r(float x) {
    return __uint_as_float(f2tf32(x));
}
__device__ __forceinline__ void mma_tf32(float* c,
    unsigned a0, unsigned a1, unsigned a2, unsigned a3,
    unsigned b0, unsigned b1)
{
    asm volatile(
        "mma.sync.aligned.m16n8k8.row.col.f32.tf32.tf32.f32 "
        "{%0,%1,%2,%3}, {%4,%5,%6,%7}, {%8,%9}, {%0,%1,%2,%3};"
        : "+f"(c[0]), "+f"(c[1]), "+f"(c[2]), "+f"(c[3])
        : "r"(a0), "r"(a1), "r"(a2), "r"(a3), "r"(b0), "r"(b1));
}
__device__ __forceinline__ void cp_async16(unsigned dst, const void* src, int srcsize) {
    asm volatile("cp.async.cg.shared.global [%0], [%1], 16, %2;"
                 :: "r"(dst), "l"(src), "r"(srcsize));
}
__device__ __forceinline__ void cp_commit() {
    asm volatile("cp.async.commit_group;");
}

// ---------------------------------------------------------------------------
// GEMM tile body: C[tile] = (A @ W^T + bias) * scale  [optionally tf32-rounded]
// Block 256 thr (8 warps, 2m x 4n), tile 128x128, BK=16.
// Ping-pong double-buffered smem: ONE barrier per K-iter, LDG overlapped.
// ---------------------------------------------------------------------------
#define GBK 16
#define GAS 20   // As stride (floats)
#define GBS 20   // Bs stride

struct GemmSmem {
    float As[2][128 * GAS];
    float Bs[2][128 * GBS];
};

__device__ __forceinline__ void gemm_tile_body(
    const float* __restrict__ A,
    const float* __restrict__ W,
    const float* __restrict__ bias,
    float* __restrict__ C,
    int m0, int n0, int M, float scale, bool rnd_out,
    GemmSmem& s)
{
    const int tid = threadIdx.x;
    const int w = tid >> 5;
    const int l = tid & 31;
    const int g = l >> 2;
    const int t = l & 3;
    const int wm = (w >> 2) * 64;
    const int wn = (w & 3) * 32;

    int row_[2], c4_[2];
#pragma unroll
    for (int it = 0; it < 2; it++) {
        int slot = tid + 256 * it;
        row_[it] = slot >> 2;
        c4_[it]  = (slot & 3) * 4;
    }

    float acc[4][4][4];
#pragma unroll
    for (int i = 0; i < 4; i++)
#pragma unroll
        for (int j = 0; j < 4; j++)
#pragma unroll
            for (int r = 0; r < 4; r++) acc[i][j][r] = 0.f;

    // prologue: load + store k0 = 0 into buffer 0
    {
#pragma unroll
        for (int it = 0; it < 2; it++) {
            float4 av = make_float4(0.f, 0.f, 0.f, 0.f);
            if (m0 + row_[it] < M)
                av = *(const float4*)(A + (size_t)(m0 + row_[it]) * D + c4_[it]);
            float4 bv = *(const float4*)(W + (size_t)(n0 + row_[it]) * D + c4_[it]);
            av.x = tf32r(av.x); av.y = tf32r(av.y);
            av.z = tf32r(av.z); av.w = tf32r(av.w);
            bv.x = tf32r(bv.x); bv.y = tf32r(bv.y);
            bv.z = tf32r(bv.z); bv.w = tf32r(bv.w);
            *(float4*)(s.As[0] + row_[it] * GAS + c4_[it]) = av;
            *(float4*)(s.Bs[0] + row_[it] * GBS + c4_[it]) = bv;
        }
    }
    __syncthreads();

    int buf = 0;
    for (int k0 = 0; k0 < D; k0 += GBK) {
        const int kn = k0 + GBK;
        float4 na[2], nb[2];
        if (kn < D) {
#pragma unroll
            for (int it = 0; it < 2; it++) {
                na[it] = make_float4(0.f, 0.f, 0.f, 0.f);
                if (m0 + row_[it] < M)
                    na[it] = *(const float4*)(A + (size_t)(m0 + row_[it]) * D + kn + c4_[it]);
                nb[it] = *(const float4*)(W + (size_t)(n0 + row_[it]) * D + kn + c4_[it]);
            }
        }

        const float* As = s.As[buf];
        const float* Bs = s.Bs[buf];
#pragma unroll
        for (int ss = 0; ss < 2; ss++) {
            const int kk = ss * 8;
            unsigned a[4][4];
#pragma unroll
            for (int i = 0; i < 4; i++) {
                int r = wm + i * 16 + g;
                a[i][0] = __float_as_uint(As[r * GAS + kk + t]);
                a[i][1] = __float_as_uint(As[(r + 8) * GAS + kk + t]);
                a[i][2] = __float_as_uint(As[r * GAS + kk + t + 4]);
                a[i][3] = __float_as_uint(As[(r + 8) * GAS + kk + t + 4]);
            }
#pragma unroll
            for (int j = 0; j < 4; j++) {
                int n = wn + j * 8 + g;
                unsigned b0 = __float_as_uint(Bs[n * GBS + kk + t]);
                unsigned b1 = __float_as_uint(Bs[n * GBS + kk + t + 4]);
#pragma unroll
                for (int i = 0; i < 4; i++)
                    mma_tf32(acc[i][j], a[i][0], a[i][1], a[i][2], a[i][3], b0, b1);
            }
        }

        if (kn < D) {
            const int nb_ = buf ^ 1;
#pragma unroll
            for (int it = 0; it < 2; it++) {
                float4 av = na[it], bv = nb[it];
                av.x = tf32r(av.x); av.y = tf32r(av.y);
                av.z = tf32r(av.z); av.w = tf32r(av.w);
                bv.x = tf32r(bv.x); bv.y = tf32r(bv.y);
                bv.z = tf32r(bv.z); bv.w = tf32r(bv.w);
                *(float4*)(s.As[nb_] + row_[it] * GAS + c4_[it]) = av;
                *(float4*)(s.Bs[nb_] + row_[it] * GBS + c4_[it]) = bv;
            }
        }
        __syncthreads();
        buf ^= 1;
    }

    // epilogue (optionally tf32-round outputs so attention can cp.async them raw)
#pragma unroll
    for (int j = 0; j < 4; j++) {
        int c0 = n0 + wn + j * 8 + t * 2;
        float b0v = bias ? bias[c0] : 0.f;
        float b1v = bias ? bias[c0 + 1] : 0.f;
#pragma unroll
        for (int i = 0; i < 4; i++) {
            int r0 = m0 + wm + i * 16 + g;
            int r1 = r0 + 8;
            if (r0 < M) {
                float2 p;
                p.x = (acc[i][j][0] + b0v) * scale;
                p.y = (acc[i][j][1] + b1v) * scale;
                if (rnd_out) { p.x = tf32r(p.x); p.y = tf32r(p.y); }
                *(float2*)(C + (size_t)r0 * D + c0) = p;
            }
            if (r1 < M) {
                float2 p;
                p.x = (acc[i][j][2] + b0v) * scale;
                p.y = (acc[i][j][3] + b1v) * scale;
                if (rnd_out) { p.x = tf32r(p.x); p.y = tf32r(p.y); }
                *(float2*)(C + (size_t)r1 * D + c0) = p;
            }
        }
    }
}

// Fused QKV: grid (6, 34, 3). y==33 is the det tile (rows 4201..4300).
__global__ void __launch_bounds__(256, 2) qkv_gemm(
    const float* __restrict__ x,
    const float* __restrict__ wq_p, const float* __restrict__ wq_d,
    const float* __restrict__ wk_p, const float* __restrict__ wk_d,
    const float* __restrict__ wv_p, const float* __restrict__ wv_d,
    const float* __restrict__ bq_p, const float* __restrict__ bq_d,
    const float* __restrict__ bv_p, const float* __restrict__ bv_d,
    float* __restrict__ q, float* __restrict__ k, float* __restrict__ v)
{
    __shared__ GemmSmem s;
    const bool det = (blockIdx.y == gridDim.y - 1);
    const int m0 = det ? NP : blockIdx.y * 128;
    const int M  = det ? N_TOK : NP;
    const int z = blockIdx.z;

    const float* W;
    const float* bias;
    float* C;
    float scale = 1.f;
    if (z == 0) {
        W = det ? wq_d : wq_p; bias = det ? bq_d : bq_p; C = q; scale = QSCALE;
    } else if (z == 1) {
        W = det ? wk_d : wk_p; bias = nullptr; C = k;
    } else {
        W = det ? wv_d : wv_p; bias = det ? bv_d : bv_p; C = v;
    }
    // outputs tf32-rounded: attention consumes them raw via cp.async
    gemm_tile_body(x, W, bias, C, m0, blockIdx.x * 128, M, scale, true, s);
}

// Fused out-projection: grid (6, 34). y==33 is the det tile.
__global__ void __launch_bounds__(256, 2) out_gemm(
    const float* __restrict__ A,
    const float* __restrict__ wo_p, const float* __restrict__ wo_d,
    const float* __restrict__ bo_p, const float* __restrict__ bo_d,
    float* __restrict__ C)
{
    __shared__ GemmSmem s;
    const bool det = (blockIdx.y == gridDim.y - 1);
    const int m0 = det ? NP : blockIdx.y * 128;
    const int M  = det ? N_TOK : NP;
    gemm_tile_body(A, det ? wo_d : wo_p, det ? bo_d : bo_p, C,
                   m0, blockIdx.x * 128, M, 1.f, false, s);
}

// ---------------------------------------------------------------------------
// Tensor-core flash attention (tf32), cp.async pipelined, 2 CTAs/SM.
// K single-buffered (prefetched during softmax+PV phase), V double-buffered.
// Block: 256 thr (8 warps), 128 queries x one head. Warp owns 16 q rows.
// Inputs q/k/v are pre-rounded to tf32 by the QKV GEMM epilogue.
// ---------------------------------------------------------------------------
#define QS_S 68
#define KS_S 68
#define VS_S 72
#define NKT ((N_TOK + 63) / 64)   // 68 key tiles
#define ATT_SMEM ((128 * QS_S + 64 * KS_S + 2 * 64 * VS_S) * 4)

__global__ void __launch_bounds__(256, 2) attn_tc(
    const float* __restrict__ q, const float* __restrict__ k,
    const float* __restrict__ v, float* __restrict__ o)
{
    extern __shared__ float sm[];
    float* Qs = sm;                                   // [128][QS_S]
    float* Ks = sm + 128 * QS_S;                      // [64][KS_S] single buf
    float* Vs0 = Ks + 64 * KS_S;                      // [2][64][VS_S]

    const int h = blockIdx.y;
    const int q0 = blockIdx.x * 128;
    const int tid = threadIdx.x;
    const int w = tid >> 5;
    const int l = tid & 31;
    const int g = l >> 2;
    const int t = l & 3;
    const int r0 = w * 16 + g;

    // per-thread K/V chunk coords (4 chunks each of 16B)
    int kr_[4], kc_[4];
#pragma unroll
    for (int it = 0; it < 4; it++) {
        int slot = tid + 256 * it;      // 1024 float4 slots
        kr_[it] = slot >> 4;            // 0..63
        kc_[it] = (slot & 15) * 4;
    }
    unsigned ks_u32 = (unsigned)__cvta_generic_to_shared(Ks);
    unsigned vs_u32 = (unsigned)__cvta_generic_to_shared(Vs0);

    // prologue: prefetch K0 + V0 (tile 0 is full: 64 rows)
#pragma unroll
    for (int it = 0; it < 4; it++) {
        int row = kr_[it], c4 = kc_[it];
        cp_async16(ks_u32 + (row * KS_S + c4) * 4,
                   k + (size_t)row * D + h * HD + c4, 16);
        cp_async16(vs_u32 + (row * VS_S + c4) * 4,
                   v + (size_t)row * D + h * HD + c4, 16);
    }
    cp_commit();

    // Load Q tile (pre-rounded, zero-padded)
#pragma unroll
    for (int it = 0; it < 8; it++) {
        int slot = tid + 256 * it;      // 2048 float4 slots
        int row = slot >> 4;
        int c4 = (slot & 15) * 4;
        float4 val = make_float4(0.f, 0.f, 0.f, 0.f);
        if (q0 + row < N_TOK)
            val = *(const float4*)(q + (size_t)(q0 + row) * D + h * HD + c4);
        *(float4*)(Qs + row * QS_S + c4) = val;
    }

    float m0 = -1e30f, m1 = -1e30f, l0 = 0.f, l1 = 0.f;
    float oacc[8][4];
#pragma unroll
    for (int n = 0; n < 8; n++)
#pragma unroll
        for (int r = 0; r < 4; r++) oacc[n][r] = 0.f;

    const int srcA = (l & ~3) | (t >> 1);
    const int srcB = srcA + 2;
    const bool odd = (t & 1);

    for (int ti = 0; ti < NKT; ti++) {
        const int t0 = ti * 64;
        const int cnt = min(64, N_TOK - t0);
        const int buf = ti & 1;
        const float* Vs = Vs0 + buf * 64 * VS_S;

        // wait for K[ti] + V[ti]; barrier makes them visible block-wide.
        asm volatile("cp.async.wait_group 0;");
        __syncthreads();

        // S = Q @ K^T
        float sc[8][4];
#pragma unroll
        for (int n = 0; n < 8; n++)
#pragma unroll
            for (int r = 0; r < 4; r++) sc[n][r] = 0.f;

#pragma unroll
        for (int s = 0; s < 8; s++) {
            unsigned a0 = __float_as_uint(Qs[r0 * QS_S + s * 8 + t]);
            unsigned a1 = __float_as_uint(Qs[(r0 + 8) * QS_S + s * 8 + t]);
            unsigned a2 = __float_as_uint(Qs[r0 * QS_S + s * 8 + t + 4]);
            unsigned a3 = __float_as_uint(Qs[(r0 + 8) * QS_S + s * 8 + t + 4]);
#pragma unroll
            for (int n = 0; n < 8; n++) {
                unsigned b0 = __float_as_uint(Ks[(n * 8 + g) * KS_S + s * 8 + t]);
                unsigned b1 = __float_as_uint(Ks[(n * 8 + g) * KS_S + s * 8 + t + 4]);
                mma_tf32(sc[n], a0, a1, a2, a3, b0, b1);
            }
        }

        // K consumed by all warps -> safe to overwrite with K[ti+1]
        __syncthreads();
        if (ti + 1 < NKT) {
            const int nt0 = t0 + 64;
            const int ncnt = min(64, N_TOK - nt0);
            const unsigned vb = vs_u32 + (buf ^ 1) * 64 * VS_S * 4;
#pragma unroll
            for (int it = 0; it < 4; it++) {
                int row = kr_[it], c4 = kc_[it];
                int ok = (row < ncnt) ? 16 : 0;
                size_t off = (size_t)(nt0 + (ok ? row : 0)) * D + h * HD + c4;
                cp_async16(ks_u32 + (row * KS_S + c4) * 4, k + off, ok);
                cp_async16(vb + (row * VS_S + c4) * 4, v + off, ok);
            }
            cp_commit();
        }

        // Mask padded keys (last tile only)
        if (cnt < 64) {
#pragma unroll
            for (int n = 0; n < 8; n++) {
                int j0 = n * 8 + t * 2;
                if (j0 >= cnt)     { sc[n][0] = -1e30f; sc[n][2] = -1e30f; }
                if (j0 + 1 >= cnt) { sc[n][1] = -1e30f; sc[n][3] = -1e30f; }
            }
        }

        // Online softmax (rows r0, r0+8)
        float mx0 = -1e30f, mx1 = -1e30f;
#pragma unroll
        for (int n = 0; n < 8; n++) {
            mx0 = fmaxf(mx0, fmaxf(sc[n][0], sc[n][1]));
            mx1 = fmaxf(mx1, fmaxf(sc[n][2], sc[n][3]));
        }
        mx0 = fmaxf(mx0, __shfl_xor_sync(0xffffffffu, mx0, 1));
        mx0 = fmaxf(mx0, __shfl_xor_sync(0xffffffffu, mx0, 2));
        mx1 = fmaxf(mx1, __shfl_xor_sync(0xffffffffu, mx1, 1));
        mx1 = fmaxf(mx1, __shfl_xor_sync(0xffffffffu, mx1, 2));
        float nm0 = fmaxf(m0, mx0), nm1 = fmaxf(m1, mx1);
        float esc0 = __expf(m0 - nm0), esc1 = __expf(m1 - nm1);
        m0 = nm0; m1 = nm1;

        float sum0 = 0.f, sum1 = 0.f;
#pragma unroll
        for (int n = 0; n < 8; n++) {
            sc[n][0] = __expf(sc[n][0] - m0);
            sc[n][1] = __expf(sc[n][1] - m0);
            sc[n][2] = __expf(sc[n][2] - m1);
            sc[n][3] = __expf(sc[n][3] - m1);
            sum0 += sc[n][0] + sc[n][1];
            sum1 += sc[n][2] + sc[n][3];
        }
        sum0 += __shfl_xor_sync(0xffffffffu, sum0, 1);
        sum0 += __shfl_xor_sync(0xffffffffu, sum0, 2);
        sum1 += __shfl_xor_sync(0xffffffffu, sum1, 1);
        sum1 += __shfl_xor_sync(0xffffffffu, sum1, 2);
        l0 = l0 * esc0 + sum0;
        l1 = l1 * esc1 + sum1;

        if (__any_sync(0xffffffffu, (esc0 != 1.f) || (esc1 != 1.f))) {
#pragma unroll
            for (int n = 0; n < 8; n++) {
                oacc[n][0] *= esc0; oacc[n][1] *= esc0;
                oacc[n][2] *= esc1; oacc[n][3] *= esc1;
            }
        }

        // O += P @ V  (reads Vs[buf]; next tile's V goes to the other buffer)
#pragma unroll
        for (int s = 0; s < 8; s++) {
            float v00 = __shfl_sync(0xffffffffu, sc[s][0], srcA);
            float v01 = __shfl_sync(0xffffffffu, sc[s][1], srcA);
            float v10 = __shfl_sync(0xffffffffu, sc[s][2], srcA);
            float v11 = __shfl_sync(0xffffffffu, sc[s][3], srcA);
            float w00 = __shfl_sync(0xffffffffu, sc[s][0], srcB);
            float w01 = __shfl_sync(0xffffffffu, sc[s][1], srcB);
            float w10 = __shfl_sync(0xffffffffu, sc[s][2], srcB);
            float w11 = __shfl_sync(0xffffffffu, sc[s][3], srcB);
            unsigned a0 = f2tf32(odd ? v01 : v00);
            unsigned a1 = f2tf32(odd ? v11 : v10);
            unsigned a2 = f2tf32(odd ? w01 : w00);
            unsigned a3 = f2tf32(odd ? w11 : w10);
#pragma unroll
            for (int n = 0; n < 8; n++) {
                unsigned b0 = __float_as_uint(Vs[(s * 8 + t) * VS_S + n * 8 + g]);
                unsigned b1 = __float_as_uint(Vs[(s * 8 + t + 4) * VS_S + n * 8 + g]);
                mma_tf32(oacc[n], a0, a1, a2, a3, b0, b1);
            }
        }
        // no trailing barrier: next iteration's wait_group + __syncthreads
        // orders the K overwrite (K reads already fenced above) and V[buf^1]
        // writes (that buffer was last read two tiles ago).
    }

    // Epilogue
    float i0 = 1.f / l0, i1 = 1.f / l1;
    int gr0 = q0 + r0, gr1 = gr0 + 8;
#pragma unroll
    for (int n = 0; n < 8; n++) {
        int c = h * HD + n * 8 + t * 2;
        if (gr0 < N_TOK) {
            float2 p;
            p.x = oacc[n][0] * i0; p.y = oacc[n][1] * i0;
            *(float2*)(o + (size_t)gr0 * D + c) = p;
        }
        if (gr1 < N_TOK) {
            float2 p;
            p.x = oacc[n][2] * i1; p.y = oacc[n][3] * i1;
            *(float2*)(o + (size_t)gr1 * D + c) = p;
        }
    }
}

// ---------------------------------------------------------------------------
// LayerNorm (in place): one block per token row.
// ---------------------------------------------------------------------------
__global__ void __launch_bounds__(256) ln_kernel(
    float* __restrict__ o, const float* __restrict__ g, const float* __restrict__ b)
{
    const int row = blockIdx.x;
    float* p = o + (size_t)row * D;
    const int t = threadIdx.x;
    float x0 = p[t], x1 = p[t + 256], x2 = p[t + 512];
    float s = x0 + x1 + x2;
    float sq = x0 * x0 + x1 * x1 + x2 * x2;

    __shared__ float red[64];
#pragma unroll
    for (int off = 16; off > 0; off >>= 1) {
        s  += __shfl_down_sync(0xffffffffu, s, off);
        sq += __shfl_down_sync(0xffffffffu, sq, off);
    }
    int wid = t >> 5, lid = t & 31;
    if (lid == 0) { red[wid] = s; red[wid + 32] = sq; }
    __syncthreads();
    __shared__ float mu_s, rstd_s;
    if (t == 0) {
        float S = 0.f, SQ = 0.f;
#pragma unroll
        for (int i = 0; i < 8; i++) { S += red[i]; SQ += red[i + 32]; }
        float mu = S * (1.f / D);
        float var = SQ * (1.f / D) - mu * mu;
        mu_s = mu;
        rstd_s = rsqrtf(var + 1e-5f);
    }
    __syncthreads();
    float mu = mu_s, r = rstd_s;
    p[t]       = (x0 - mu) * r * g[t]       + b[t];
    p[t + 256] = (x1 - mu) * r * g[t + 256] + b[t + 256];
    p[t + 512] = (x2 - mu) * r * g[t + 512] + b[t + 512];
}

// ---------------------------------------------------------------------------
extern "C" void kernel_launch(void* const* d_in, const int* in_sizes, int n_in,
                              void* d_out, int out_size)
{
    const float* x    = (const float*)d_in[0];
    const float* wq_p = (const float*)d_in[1];
    const float* wk_p = (const float*)d_in[2];
    const float* wv_p = (const float*)d_in[3];
    const float* wq_d = (const float*)d_in[4];
    const float* wk_d = (const float*)d_in[5];
    const float* wv_d = (const float*)d_in[6];
    const float* bq_p = (const float*)d_in[7];
    const float* bv_p = (const float*)d_in[8];
    const float* bq_d = (const float*)d_in[9];
    const float* bv_d = (const float*)d_in[10];
    const float* ln_g = (const float*)d_in[11];
    const float* ln_b = (const float*)d_in[12];
    const float* wo_p = (const float*)d_in[13];
    const float* bo_p = (const float*)d_in[14];
    const float* wo_d = (const float*)d_in[15];
    const float* bo_d = (const float*)d_in[16];
    float* out = (float*)d_out;

    float *q, *k, *v, *o;
    cudaGetSymbolAddress((void**)&q, g_q);
    cudaGetSymbolAddress((void**)&k, g_k);
    cudaGetSymbolAddress((void**)&v, g_v);
    cudaGetSymbolAddress((void**)&o, g_o);

    cudaFuncSetAttribute(attn_tc, cudaFuncAttributeMaxDynamicSharedMemorySize, ATT_SMEM);

    // Fused QKV projections: 6 x 34 x 3 = 612 blocks, one launch.
    dim3 gq(D / 128, 34, 3);
    qkv_gemm<<<gq, 256>>>(x, wq_p, wq_d, wk_p, wk_d, wv_p, wv_d,
                          bq_p, bq_d, bv_p, bv_d, q, k, v);

    // Attention (tensor-core flash, K single / V double buffered, 2 CTAs/SM)
    dim3 ga((N_TOK + 127) / 128, H);      // (34, 12)
    attn_tc<<<ga, 256, ATT_SMEM>>>(q, k, v, o);

    // LayerNorm (in place on o)
    ln_kernel<<<N_TOK, 256>>>(o, ln_g, ln_b);

    // Output projection (patch + det fused)
    dim3 go(D / 128, 34);
    out_gemm<<<go, 256>>>(o, wo_p, wo_d, bo_p, bo_d, out);
}

// round 13
// speedup vs baseline: 1.7452x; 1.5152x over previous
#include <cuda_runtime.h>
#include <cuda_fp16.h>
#include <math.h>

#define N_TOK 4301
#define NP    4201
#define ND    100
#define D     768
#define H     12
#define HD    64
#define QSCALE 0.125f

// Scratch (allocation-free rule: __device__ globals)
__device__ __half g_q[(size_t)N_TOK * D];
__device__ __half g_k[(size_t)N_TOK * D];
__device__ __half g_v[(size_t)N_TOK * D];
__device__ float  g_o[(size_t)N_TOK * D];

// ---------------------------------------------------------------------------
// helpers
// ---------------------------------------------------------------------------
__device__ __forceinline__ unsigned f2tf32(float x) {
    unsigned u;
    asm("cvt.rna.tf32.f32 %0, %1;" : "=r"(u) : "f"(x));
    return u;
}
__device__ __forceinline__ float tf32r(float x) {
    return __uint_as_float(f2tf32(x));
}
__device__ __forceinline__ void mma_tf32(float* c,
    unsigned a0, unsigned a1, unsigned a2, unsigned a3,
    unsigned b0, unsigned b1)
{
    asm volatile(
        "mma.sync.aligned.m16n8k8.row.col.f32.tf32.tf32.f32 "
        "{%0,%1,%2,%3}, {%4,%5,%6,%7}, {%8,%9}, {%0,%1,%2,%3};"
        : "+f"(c[0]), "+f"(c[1]), "+f"(c[2]), "+f"(c[3])
        : "r"(a0), "r"(a1), "r"(a2), "r"(a3), "r"(b0), "r"(b1));
}
__device__ __forceinline__ void mma_f16(float* c,
    unsigned a0, unsigned a1, unsigned a2, unsigned a3,
    unsigned b0, unsigned b1)
{
    asm volatile(
        "mma.sync.aligned.m16n8k16.row.col.f32.f16.f16.f32 "
        "{%0,%1,%2,%3}, {%4,%5,%6,%7}, {%8,%9}, {%0,%1,%2,%3};"
        : "+f"(c[0]), "+f"(c[1]), "+f"(c[2]), "+f"(c[3])
        : "r"(a0), "r"(a1), "r"(a2), "r"(a3), "r"(b0), "r"(b1));
}
__device__ __forceinline__ void ldsm_x4(unsigned& r0, unsigned& r1,
                                        unsigned& r2, unsigned& r3, unsigned addr)
{
    asm volatile("ldmatrix.sync.aligned.m8n8.x4.shared.b16 {%0,%1,%2,%3}, [%4];"
                 : "=r"(r0), "=r"(r1), "=r"(r2), "=r"(r3) : "r"(addr));
}
__device__ __forceinline__ void ldsm_x4_t(unsigned& r0, unsigned& r1,
                                          unsigned& r2, unsigned& r3, unsigned addr)
{
    asm volatile("ldmatrix.sync.aligned.m8n8.x4.trans.shared.b16 {%0,%1,%2,%3}, [%4];"
                 : "=r"(r0), "=r"(r1), "=r"(r2), "=r"(r3) : "r"(addr));
}
__device__ __forceinline__ unsigned packh2(float lo, float hi) {
    __half2 h = __floats2half2_rn(lo, hi);
    return *(unsigned*)&h;
}
__device__ __forceinline__ void cp_async16(unsigned dst, const void* src, int srcsize) {
    asm volatile("cp.async.cg.shared.global [%0], [%1], 16, %2;"
                 :: "r"(dst), "l"(src), "r"(srcsize));
}
__device__ __forceinline__ void cp_commit() {
    asm volatile("cp.async.commit_group;");
}

// ---------------------------------------------------------------------------
// GEMM tile body (tf32 mma): C = (A @ W^T + bias) * scale
// Block 256 thr (8 warps, 2m x 4n), tile 128x128, BK=16, ping-pong smem.
// HALF_OUT: write fp16 (for q/k/v consumed by attention) else fp32.
// ---------------------------------------------------------------------------
#define GBK 16
#define GAS 20
#define GBS 20

struct GemmSmem {
    float As[2][128 * GAS];
    float Bs[2][128 * GBS];
};

template <bool HALF_OUT>
__device__ __forceinline__ void gemm_tile_body(
    const float* __restrict__ A,
    const float* __restrict__ W,
    const float* __restrict__ bias,
    float* __restrict__ Cf, __half* __restrict__ Ch,
    int m0, int n0, int M, float scale,
    GemmSmem& s)
{
    const int tid = threadIdx.x;
    const int w = tid >> 5;
    const int l = tid & 31;
    const int g = l >> 2;
    const int t = l & 3;
    const int wm = (w >> 2) * 64;
    const int wn = (w & 3) * 32;

    int row_[2], c4_[2];
#pragma unroll
    for (int it = 0; it < 2; it++) {
        int slot = tid + 256 * it;
        row_[it] = slot >> 2;
        c4_[it]  = (slot & 3) * 4;
    }

    float acc[4][4][4];
#pragma unroll
    for (int i = 0; i < 4; i++)
#pragma unroll
        for (int j = 0; j < 4; j++)
#pragma unroll
            for (int r = 0; r < 4; r++) acc[i][j][r] = 0.f;

    {
#pragma unroll
        for (int it = 0; it < 2; it++) {
            float4 av = make_float4(0.f, 0.f, 0.f, 0.f);
            if (m0 + row_[it] < M)
                av = *(const float4*)(A + (size_t)(m0 + row_[it]) * D + c4_[it]);
            float4 bv = *(const float4*)(W + (size_t)(n0 + row_[it]) * D + c4_[it]);
            av.x = tf32r(av.x); av.y = tf32r(av.y);
            av.z = tf32r(av.z); av.w = tf32r(av.w);
            bv.x = tf32r(bv.x); bv.y = tf32r(bv.y);
            bv.z = tf32r(bv.z); bv.w = tf32r(bv.w);
            *(float4*)(s.As[0] + row_[it] * GAS + c4_[it]) = av;
            *(float4*)(s.Bs[0] + row_[it] * GBS + c4_[it]) = bv;
        }
    }
    __syncthreads();

    int buf = 0;
    for (int k0 = 0; k0 < D; k0 += GBK) {
        const int kn = k0 + GBK;
        float4 na[2], nb[2];
        if (kn < D) {
#pragma unroll
            for (int it = 0; it < 2; it++) {
                na[it] = make_float4(0.f, 0.f, 0.f, 0.f);
                if (m0 + row_[it] < M)
                    na[it] = *(const float4*)(A + (size_t)(m0 + row_[it]) * D + kn + c4_[it]);
                nb[it] = *(const float4*)(W + (size_t)(n0 + row_[it]) * D + kn + c4_[it]);
            }
        }

        const float* As = s.As[buf];
        const float* Bs = s.Bs[buf];
#pragma unroll
        for (int ss = 0; ss < 2; ss++) {
            const int kk = ss * 8;
            unsigned a[4][4];
#pragma unroll
            for (int i = 0; i < 4; i++) {
                int r = wm + i * 16 + g;
                a[i][0] = __float_as_uint(As[r * GAS + kk + t]);
                a[i][1] = __float_as_uint(As[(r + 8) * GAS + kk + t]);
                a[i][2] = __float_as_uint(As[r * GAS + kk + t + 4]);
                a[i][3] = __float_as_uint(As[(r + 8) * GAS + kk + t + 4]);
            }
#pragma unroll
            for (int j = 0; j < 4; j++) {
                int n = wn + j * 8 + g;
                unsigned b0 = __float_as_uint(Bs[n * GBS + kk + t]);
                unsigned b1 = __float_as_uint(Bs[n * GBS + kk + t + 4]);
#pragma unroll
                for (int i = 0; i < 4; i++)
                    mma_tf32(acc[i][j], a[i][0], a[i][1], a[i][2], a[i][3], b0, b1);
            }
        }

        if (kn < D) {
            const int nb_ = buf ^ 1;
#pragma unroll
            for (int it = 0; it < 2; it++) {
                float4 av = na[it], bv = nb[it];
                av.x = tf32r(av.x); av.y = tf32r(av.y);
                av.z = tf32r(av.z); av.w = tf32r(av.w);
                bv.x = tf32r(bv.x); bv.y = tf32r(bv.y);
                bv.z = tf32r(bv.z); bv.w = tf32r(bv.w);
                *(float4*)(s.As[nb_] + row_[it] * GAS + c4_[it]) = av;
                *(float4*)(s.Bs[nb_] + row_[it] * GBS + c4_[it]) = bv;
            }
        }
        __syncthreads();
        buf ^= 1;
    }

#pragma unroll
    for (int j = 0; j < 4; j++) {
        int c0 = n0 + wn + j * 8 + t * 2;
        float b0v = bias ? bias[c0] : 0.f;
        float b1v = bias ? bias[c0 + 1] : 0.f;
#pragma unroll
        for (int i = 0; i < 4; i++) {
            int r0 = m0 + wm + i * 16 + g;
            int r1 = r0 + 8;
            if (r0 < M) {
                float px = (acc[i][j][0] + b0v) * scale;
                float py = (acc[i][j][1] + b1v) * scale;
                if (HALF_OUT)
                    *(__half2*)(Ch + (size_t)r0 * D + c0) = __floats2half2_rn(px, py);
                else
                    *(float2*)(Cf + (size_t)r0 * D + c0) = make_float2(px, py);
            }
            if (r1 < M) {
                float px = (acc[i][j][2] + b0v) * scale;
                float py = (acc[i][j][3] + b1v) * scale;
                if (HALF_OUT)
                    *(__half2*)(Ch + (size_t)r1 * D + c0) = __floats2half2_rn(px, py);
                else
                    *(float2*)(Cf + (size_t)r1 * D + c0) = make_float2(px, py);
            }
        }
    }
}

// Fused QKV: grid (6, 34, 3). y==33 is the det tile (rows 4201..4300).
__global__ void __launch_bounds__(256, 2) qkv_gemm(
    const float* __restrict__ x,
    const float* __restrict__ wq_p, const float* __restrict__ wq_d,
    const float* __restrict__ wk_p, const float* __restrict__ wk_d,
    const float* __restrict__ wv_p, const float* __restrict__ wv_d,
    const float* __restrict__ bq_p, const float* __restrict__ bq_d,
    const float* __restrict__ bv_p, const float* __restrict__ bv_d,
    __half* __restrict__ q, __half* __restrict__ k, __half* __restrict__ v)
{
    __shared__ GemmSmem s;
    const bool det = (blockIdx.y == gridDim.y - 1);
    const int m0 = det ? NP : blockIdx.y * 128;
    const int M  = det ? N_TOK : NP;
    const int z = blockIdx.z;

    const float* W;
    const float* bias;
    __half* C;
    float scale = 1.f;
    if (z == 0) {
        W = det ? wq_d : wq_p; bias = det ? bq_d : bq_p; C = q; scale = QSCALE;
    } else if (z == 1) {
        W = det ? wk_d : wk_p; bias = nullptr; C = k;
    } else {
        W = det ? wv_d : wv_p; bias = det ? bv_d : bv_p; C = v;
    }
    gemm_tile_body<true>(x, W, bias, nullptr, C, m0, blockIdx.x * 128, M, scale, s);
}

// Fused out-projection: grid (6, 34). y==33 is the det tile.
__global__ void __launch_bounds__(256, 2) out_gemm(
    const float* __restrict__ A,
    const float* __restrict__ wo_p, const float* __restrict__ wo_d,
    const float* __restrict__ bo_p, const float* __restrict__ bo_d,
    float* __restrict__ C)
{
    __shared__ GemmSmem s;
    const bool det = (blockIdx.y == gridDim.y - 1);
    const int m0 = det ? NP : blockIdx.y * 128;
    const int M  = det ? N_TOK : NP;
    gemm_tile_body<false>(A, det ? wo_d : wo_p, det ? bo_d : bo_p, C, nullptr,
                          m0, blockIdx.x * 128, M, 1.f, s);
}

// ---------------------------------------------------------------------------
// fp16 tensor-core flash attention (m16n8k16, fp32 accum).
// Block: 256 thr (8 warps), 128 queries x one head; warp owns 16 q rows.
// Q a-frags held in registers for the whole loop (no Q smem).
// K b-frags via ldmatrix.x4; V b-frags via ldmatrix.x4.trans (free transpose).
// P C-frags ARE the PV A-frags (pack only, no shuffles).
// K single-buffered, V double-buffered via cp.async (R7 pipeline).
// ---------------------------------------------------------------------------
#define KH 72   // halves per K row (144B, conflict-free for ldmatrix)
#define VH 72
#define NKT ((N_TOK + 63) / 64)
#define ATT_SMEM ((64 * KH + 2 * 64 * VH) * 2)

__global__ void __launch_bounds__(256, 2) attn_tc(
    const __half* __restrict__ q, const __half* __restrict__ k,
    const __half* __restrict__ v, float* __restrict__ o)
{
    extern __shared__ __half smh[];
    __half* Ks  = smh;                 // [64][KH]
    __half* Vs0 = smh + 64 * KH;       // [2][64][VH]

    const int h = blockIdx.y;
    const int q0 = blockIdx.x * 128;
    const int tid = threadIdx.x;
    const int w = tid >> 5;
    const int l = tid & 31;
    const int g = l >> 2;
    const int t = l & 3;
    const int wq = w * 16;
    const size_t hoff = (size_t)h * HD;

    // cp.async chunk coords: 64 rows x 8 chunks(16B) = 512 chunks, 2/thread
    int cr_[2], cc_[2];
#pragma unroll
    for (int it = 0; it < 2; it++) {
        int slot = tid + 256 * it;
        cr_[it] = slot >> 3;
        cc_[it] = (slot & 7) * 8;   // halves
    }
    unsigned ks_u = (unsigned)__cvta_generic_to_shared(Ks);
    unsigned vs_u = (unsigned)__cvta_generic_to_shared(Vs0);

    // prefetch K0 + V0 (tile 0 full)
#pragma unroll
    for (int it = 0; it < 2; it++) {
        cp_async16(ks_u + (cr_[it] * KH + cc_[it]) * 2,
                   k + (size_t)cr_[it] * D + hoff + cc_[it], 16);
        cp_async16(vs_u + (cr_[it] * VH + cc_[it]) * 2,
                   v + (size_t)cr_[it] * D + hoff + cc_[it], 16);
    }
    cp_commit();

    // Q a-frags in registers for the whole kernel (16 x b32)
    unsigned aq[4][4];
    {
        int gr0 = q0 + wq + g, gr1 = gr0 + 8;
        bool v0 = gr0 < N_TOK, v1 = gr1 < N_TOK;
        const __half* q0p = q + (size_t)gr0 * D + hoff;
        const __half* q1p = q + (size_t)gr1 * D + hoff;
#pragma unroll
        for (int s = 0; s < 4; s++) {
            int c0 = s * 16 + 2 * t;
            aq[s][0] = v0 ? *(const unsigned*)(q0p + c0) : 0u;
            aq[s][1] = v1 ? *(const unsigned*)(q1p + c0) : 0u;
            aq[s][2] = v0 ? *(const unsigned*)(q0p + c0 + 8) : 0u;
            aq[s][3] = v1 ? *(const unsigned*)(q1p + c0 + 8) : 0u;
        }
    }

    // ldmatrix lane offsets (in halves)
    const int lk = (((l >> 4) << 3) + (l & 7)) * KH + ((l >> 3) & 1) * 8;
    const int lv = ((((l >> 3) & 1) << 3) + (l & 7)) * VH + ((l >> 4) << 3);

    float m0 = -1e30f, m1 = -1e30f, l0 = 0.f, l1 = 0.f;
    float oacc[8][4];
#pragma unroll
    for (int n = 0; n < 8; n++)
#pragma unroll
        for (int r = 0; r < 4; r++) oacc[n][r] = 0.f;

    for (int ti = 0; ti < NKT; ti++) {
        const int t0 = ti * 64;
        const int cnt = min(64, N_TOK - t0);
        const int buf = ti & 1;
        const unsigned vb_u = vs_u + buf * 64 * VH * 2;

        asm volatile("cp.async.wait_group 0;");
        __syncthreads();

        // S = Q @ K^T  (fp16 mma, K=16 per step)
        float sc[8][4];
#pragma unroll
        for (int n = 0; n < 8; n++)
#pragma unroll
            for (int r = 0; r < 4; r++) sc[n][r] = 0.f;

#pragma unroll
        for (int s = 0; s < 4; s++) {
#pragma unroll
            for (int np = 0; np < 4; np++) {
                unsigned b0, b1, b2, b3;
                ldsm_x4(b0, b1, b2, b3,
                        ks_u + (np * 16 * KH + s * 16 + lk) * 2);
                mma_f16(sc[2 * np],     aq[s][0], aq[s][1], aq[s][2], aq[s][3], b0, b1);
                mma_f16(sc[2 * np + 1], aq[s][0], aq[s][1], aq[s][2], aq[s][3], b2, b3);
            }
        }

        // K consumed by all warps -> safe to overwrite with K[ti+1]
        __syncthreads();
        if (ti + 1 < NKT) {
            const int nt0 = t0 + 64;
            const int ncnt = min(64, N_TOK - nt0);
            const unsigned vb2 = vs_u + (buf ^ 1) * 64 * VH * 2;
#pragma unroll
            for (int it = 0; it < 2; it++) {
                int row = cr_[it], cc = cc_[it];
                int ok = (row < ncnt) ? 16 : 0;
                size_t off = (size_t)(nt0 + (ok ? row : 0)) * D + hoff + cc;
                cp_async16(ks_u + (row * KH + cc) * 2, k + off, ok);
                cp_async16(vb2 + (row * VH + cc) * 2, v + off, ok);
            }
            cp_commit();
        }

        // Mask padded keys (last tile only)
        if (cnt < 64) {
#pragma unroll
            for (int n = 0; n < 8; n++) {
                int j0 = n * 8 + t * 2;
                if (j0 >= cnt)     { sc[n][0] = -1e30f; sc[n][2] = -1e30f; }
                if (j0 + 1 >= cnt) { sc[n][1] = -1e30f; sc[n][3] = -1e30f; }
            }
        }

        // Online softmax (rows r0=wq+g, r0+8)
        float mx0 = -1e30f, mx1 = -1e30f;
#pragma unroll
        for (int n = 0; n < 8; n++) {
            mx0 = fmaxf(mx0, fmaxf(sc[n][0], sc[n][1]));
            mx1 = fmaxf(mx1, fmaxf(sc[n][2], sc[n][3]));
        }
        mx0 = fmaxf(mx0, __shfl_xor_sync(0xffffffffu, mx0, 1));
        mx0 = fmaxf(mx0, __shfl_xor_sync(0xffffffffu, mx0, 2));
        mx1 = fmaxf(mx1, __shfl_xor_sync(0xffffffffu, mx1, 1));
        mx1 = fmaxf(mx1, __shfl_xor_sync(0xffffffffu, mx1, 2));
        float nm0 = fmaxf(m0, mx0), nm1 = fmaxf(m1, mx1);
        float esc0 = __expf(m0 - nm0), esc1 = __expf(m1 - nm1);
        m0 = nm0; m1 = nm1;

        float sum0 = 0.f, sum1 = 0.f;
#pragma unroll
        for (int n = 0; n < 8; n++) {
            sc[n][0] = __expf(sc[n][0] - m0);
            sc[n][1] = __expf(sc[n][1] - m0);
            sc[n][2] = __expf(sc[n][2] - m1);
            sc[n][3] = __expf(sc[n][3] - m1);
            sum0 += sc[n][0] + sc[n][1];
            sum1 += sc[n][2] + sc[n][3];
        }
        sum0 += __shfl_xor_sync(0xffffffffu, sum0, 1);
        sum0 += __shfl_xor_sync(0xffffffffu, sum0, 2);
        sum1 += __shfl_xor_sync(0xffffffffu, sum1, 1);
        sum1 += __shfl_xor_sync(0xffffffffu, sum1, 2);
        l0 = l0 * esc0 + sum0;
        l1 = l1 * esc1 + sum1;

        if (__any_sync(0xffffffffu, (esc0 != 1.f) || (esc1 != 1.f))) {
#pragma unroll
            for (int n = 0; n < 8; n++) {
                oacc[n][0] *= esc0; oacc[n][1] *= esc0;
                oacc[n][2] *= esc1; oacc[n][3] *= esc1;
            }
        }

        // O += P @ V : P C-frags pack directly into A-frags (no shuffles)
#pragma unroll
        for (int s = 0; s < 4; s++) {
            unsigned a0 = packh2(sc[2 * s][0],     sc[2 * s][1]);
            unsigned a1 = packh2(sc[2 * s][2],     sc[2 * s][3]);
            unsigned a2 = packh2(sc[2 * s + 1][0], sc[2 * s + 1][1]);
            unsigned a3 = packh2(sc[2 * s + 1][2], sc[2 * s + 1][3]);
#pragma unroll
            for (int np = 0; np < 4; np++) {
                unsigned b0, b1, b2, b3;
                ldsm_x4_t(b0, b1, b2, b3,
                          vb_u + (s * 16 * VH + np * 16 + lv) * 2);
                mma_f16(oacc[2 * np],     a0, a1, a2, a3, b0, b1);
                mma_f16(oacc[2 * np + 1], a0, a1, a2, a3, b2, b3);
            }
        }
        // next iteration's wait_group + __syncthreads orders the K overwrite
        // and V[buf^1] writes (last read two tiles ago).
    }

    // Epilogue
    float i0 = 1.f / l0, i1 = 1.f / l1;
    int gr0 = q0 + wq + g, gr1 = gr0 + 8;
#pragma unroll
    for (int n = 0; n < 8; n++) {
        int c = h * HD + n * 8 + t * 2;
        if (gr0 < N_TOK) {
            float2 p;
            p.x = oacc[n][0] * i0; p.y = oacc[n][1] * i0;
            *(float2*)(o + (size_t)gr0 * D + c) = p;
        }
        if (gr1 < N_TOK) {
            float2 p;
            p.x = oacc[n][2] * i1; p.y = oacc[n][3] * i1;
            *(float2*)(o + (size_t)gr1 * D + c) = p;
        }
    }
}

// ---------------------------------------------------------------------------
// LayerNorm (in place): one block per token row.
// ---------------------------------------------------------------------------
__global__ void __launch_bounds__(256) ln_kernel(
    float* __restrict__ o, const float* __restrict__ g, const float* __restrict__ b)
{
    const int row = blockIdx.x;
    float* p = o + (size_t)row * D;
    const int t = threadIdx.x;
    float x0 = p[t], x1 = p[t + 256], x2 = p[t + 512];
    float s = x0 + x1 + x2;
    float sq = x0 * x0 + x1 * x1 + x2 * x2;

    __shared__ float red[64];
#pragma unroll
    for (int off = 16; off > 0; off >>= 1) {
        s  += __shfl_down_sync(0xffffffffu, s, off);
        sq += __shfl_down_sync(0xffffffffu, sq, off);
    }
    int wid = t >> 5, lid = t & 31;
    if (lid == 0) { red[wid] = s; red[wid + 32] = sq; }
    __syncthreads();
    __shared__ float mu_s, rstd_s;
    if (t == 0) {
        float S = 0.f, SQ = 0.f;
#pragma unroll
        for (int i = 0; i < 8; i++) { S += red[i]; SQ += red[i + 32]; }
        float mu = S * (1.f / D);
        float var = SQ * (1.f / D) - mu * mu;
        mu_s = mu;
        rstd_s = rsqrtf(var + 1e-5f);
    }
    __syncthreads();
    float mu = mu_s, r = rstd_s;
    p[t]       = (x0 - mu) * r * g[t]       + b[t];
    p[t + 256] = (x1 - mu) * r * g[t + 256] + b[t + 256];
    p[t + 512] = (x2 - mu) * r * g[t + 512] + b[t + 512];
}

// ---------------------------------------------------------------------------
extern "C" void kernel_launch(void* const* d_in, const int* in_sizes, int n_in,
                              void* d_out, int out_size)
{
    const float* x    = (const float*)d_in[0];
    const float* wq_p = (const float*)d_in[1];
    const float* wk_p = (const float*)d_in[2];
    const float* wv_p = (const float*)d_in[3];
    const float* wq_d = (const float*)d_in[4];
    const float* wk_d = (const float*)d_in[5];
    const float* wv_d = (const float*)d_in[6];
    const float* bq_p = (const float*)d_in[7];
    const float* bv_p = (const float*)d_in[8];
    const float* bq_d = (const float*)d_in[9];
    const float* bv_d = (const float*)d_in[10];
    const float* ln_g = (const float*)d_in[11];
    const float* ln_b = (const float*)d_in[12];
    const float* wo_p = (const float*)d_in[13];
    const float* bo_p = (const float*)d_in[14];
    const float* wo_d = (const float*)d_in[15];
    const float* bo_d = (const float*)d_in[16];
    float* out = (float*)d_out;

    __half *q, *k, *v;
    float *o;
    cudaGetSymbolAddress((void**)&q, g_q);
    cudaGetSymbolAddress((void**)&k, g_k);
    cudaGetSymbolAddress((void**)&v, g_v);
    cudaGetSymbolAddress((void**)&o, g_o);

    cudaFuncSetAttribute(attn_tc, cudaFuncAttributeMaxDynamicSharedMemorySize, ATT_SMEM);

    // Fused QKV projections: 6 x 34 x 3 = 612 blocks, one launch (fp16 out).
    dim3 gq(D / 128, 34, 3);
    qkv_gemm<<<gq, 256>>>(x, wq_p, wq_d, wk_p, wk_d, wv_p, wv_d,
                          bq_p, bq_d, bv_p, bv_d, q, k, v);

    // Attention (fp16 tensor-core flash)
    dim3 ga((N_TOK + 127) / 128, H);      // (34, 12)
    attn_tc<<<ga, 256, ATT_SMEM>>>(q, k, v, o);

    // LayerNorm (in place on o)
    ln_kernel<<<N_TOK, 256>>>(o, ln_g, ln_b);

    // Output projection (patch + det fused)
    dim3 go(D / 128, 34);
    out_gemm<<<go, 256>>>(o, wo_p, wo_d, bo_p, bo_d, out);
}

// round 14
// speedup vs baseline: 2.2946x; 1.3148x over previous
#include <cuda_runtime.h>
#include <cuda_fp16.h>
#include <math.h>

#define N_TOK 4301
#define NP    4201
#define ND    100
#define D     768
#define H     12
#define HD    64
#define QSCALE 0.125f
#define WSZ   (D * D)

// Scratch (allocation-free rule: __device__ globals)
__device__ __half g_xh[(size_t)N_TOK * D];
__device__ __half g_wh[(size_t)8 * WSZ];     // 0=wq_p 1=wq_d 2=wk_p 3=wk_d 4=wv_p 5=wv_d 6=wo_p 7=wo_d
__device__ __half g_q[(size_t)N_TOK * D];
__device__ __half g_k[(size_t)N_TOK * D];
__device__ __half g_v[(size_t)N_TOK * D];
__device__ float  g_o[(size_t)N_TOK * D];
__device__ __half g_oh[(size_t)N_TOK * D];

// ---------------------------------------------------------------------------
// helpers
// ---------------------------------------------------------------------------
__device__ __forceinline__ void mma_f16(float* c,
    unsigned a0, unsigned a1, unsigned a2, unsigned a3,
    unsigned b0, unsigned b1)
{
    asm volatile(
        "mma.sync.aligned.m16n8k16.row.col.f32.f16.f16.f32 "
        "{%0,%1,%2,%3}, {%4,%5,%6,%7}, {%8,%9}, {%0,%1,%2,%3};"
        : "+f"(c[0]), "+f"(c[1]), "+f"(c[2]), "+f"(c[3])
        : "r"(a0), "r"(a1), "r"(a2), "r"(a3), "r"(b0), "r"(b1));
}
__device__ __forceinline__ void ldsm_x4(unsigned& r0, unsigned& r1,
                                        unsigned& r2, unsigned& r3, unsigned addr)
{
    asm volatile("ldmatrix.sync.aligned.m8n8.x4.shared.b16 {%0,%1,%2,%3}, [%4];"
                 : "=r"(r0), "=r"(r1), "=r"(r2), "=r"(r3) : "r"(addr));
}
__device__ __forceinline__ void ldsm_x4_t(unsigned& r0, unsigned& r1,
                                          unsigned& r2, unsigned& r3, unsigned addr)
{
    asm volatile("ldmatrix.sync.aligned.m8n8.x4.trans.shared.b16 {%0,%1,%2,%3}, [%4];"
                 : "=r"(r0), "=r"(r1), "=r"(r2), "=r"(r3) : "r"(addr));
}
__device__ __forceinline__ unsigned packh2(float lo, float hi) {
    __half2 h = __floats2half2_rn(lo, hi);
    return *(unsigned*)&h;
}
__device__ __forceinline__ void cp_async16(unsigned dst, const void* src, int srcsize) {
    asm volatile("cp.async.cg.shared.global [%0], [%1], 16, %2;"
                 :: "r"(dst), "l"(src), "r"(srcsize));
}
__device__ __forceinline__ void cp_commit() {
    asm volatile("cp.async.commit_group;");
}

// ---------------------------------------------------------------------------
// fp32 -> fp16 conversion pre-passes
// ---------------------------------------------------------------------------
__global__ void __launch_bounds__(256) f2h_x(
    const float* __restrict__ src, __half* __restrict__ dst, int n)
{
    int i = (blockIdx.x * 256 + threadIdx.x) * 8;
    if (i < n) {
        float4 v0 = *(const float4*)(src + i);
        float4 v1 = *(const float4*)(src + i + 4);
        __half2 h[4];
        h[0] = __floats2half2_rn(v0.x, v0.y);
        h[1] = __floats2half2_rn(v0.z, v0.w);
        h[2] = __floats2half2_rn(v1.x, v1.y);
        h[3] = __floats2half2_rn(v1.z, v1.w);
        *(uint4*)(dst + i) = *(uint4*)h;
    }
}

__global__ void __launch_bounds__(256) w2h(
    const float* __restrict__ w0, const float* __restrict__ w1,
    const float* __restrict__ w2, const float* __restrict__ w3,
    const float* __restrict__ w4, const float* __restrict__ w5,
    const float* __restrict__ w6, const float* __restrict__ w7,
    __half* __restrict__ dst)
{
    const float* src;
    switch (blockIdx.y) {
        case 0: src = w0; break; case 1: src = w1; break;
        case 2: src = w2; break; case 3: src = w3; break;
        case 4: src = w4; break; case 5: src = w5; break;
        case 6: src = w6; break; default: src = w7; break;
    }
    __half* d = dst + (size_t)blockIdx.y * WSZ;
    int i = (blockIdx.x * 256 + threadIdx.x) * 8;   // WSZ = 589824 divisible
    float4 v0 = *(const float4*)(src + i);
    float4 v1 = *(const float4*)(src + i + 4);
    __half2 h[4];
    h[0] = __floats2half2_rn(v0.x, v0.y);
    h[1] = __floats2half2_rn(v0.z, v0.w);
    h[2] = __floats2half2_rn(v1.x, v1.y);
    h[3] = __floats2half2_rn(v1.z, v1.w);
    *(uint4*)(d + i) = *(uint4*)h;
}

// ---------------------------------------------------------------------------
// fp16 GEMM tile body: C = (A @ W^T + bias) * scale
// Block 256 thr (8 warps, 2m x 4n), tile 128x128, BK=32, cp.async ping-pong,
// ldmatrix fragments, m16n8k16 fp16 mma with fp32 accumulate.
// ---------------------------------------------------------------------------
#define GNK (D / 32)   // 24 k-iters
#define HS  40         // smem row stride in halves (80B: conflict-free ldsm)

struct GemmSmemH {
    __half A[2][128 * HS];
    __half B[2][128 * HS];
};

template <bool HALF_OUT>
__device__ __forceinline__ void gemm_body_h(
    const __half* __restrict__ A, const __half* __restrict__ W,
    const float* __restrict__ bias,
    float* __restrict__ Cf, __half* __restrict__ Ch,
    int m0, int n0, int M, float scale, GemmSmemH& s)
{
    const int tid = threadIdx.x;
    const int w = tid >> 5;
    const int l = tid & 31;
    const int g = l >> 2;
    const int t = l & 3;
    const int wm = (w >> 2) * 64;
    const int wn = (w & 3) * 32;

    // cp.async coords: 128 rows x 32 halves = 512 x 16B chunks, 2 per thread
    int cr[2], cc[2];
#pragma unroll
    for (int it = 0; it < 2; it++) {
        int slot = tid + 256 * it;
        cr[it] = slot >> 2;
        cc[it] = (slot & 3) * 8;   // halves
    }
    unsigned au = (unsigned)__cvta_generic_to_shared(s.A);
    unsigned bu = (unsigned)__cvta_generic_to_shared(s.B);

    // prefetch k0 into buffer 0
#pragma unroll
    for (int it = 0; it < 2; it++) {
        int row = m0 + cr[it];
        int ok = (row < M) ? 16 : 0;
        cp_async16(au + (cr[it] * HS + cc[it]) * 2,
                   A + (size_t)(ok ? row : m0) * D + cc[it], ok);
        cp_async16(bu + (cr[it] * HS + cc[it]) * 2,
                   W + (size_t)(n0 + cr[it]) * D + cc[it], 16);
    }
    cp_commit();

    float acc[4][4][4];
#pragma unroll
    for (int i = 0; i < 4; i++)
#pragma unroll
        for (int j = 0; j < 4; j++)
#pragma unroll
            for (int r = 0; r < 4; r++) acc[i][j][r] = 0.f;

    // ldmatrix lane offsets (halves)
    const int la = (l & 15) * HS + ((l >> 4) & 1) * 8;                    // A m16k16
    const int lb = (((l >> 4) << 3) + (l & 7)) * HS + ((l >> 3) & 1) * 8; // B n16k16

    for (int ki = 0; ki < GNK; ki++) {
        asm volatile("cp.async.wait_group 0;");
        __syncthreads();
        const int buf = ki & 1;

        if (ki + 1 < GNK) {
            const int k0 = (ki + 1) * 32;
            const unsigned an = au + ((buf ^ 1) * 128 * HS) * 2;
            const unsigned bn = bu + ((buf ^ 1) * 128 * HS) * 2;
#pragma unroll
            for (int it = 0; it < 2; it++) {
                int row = m0 + cr[it];
                int ok = (row < M) ? 16 : 0;
                cp_async16(an + (cr[it] * HS + cc[it]) * 2,
                           A + (size_t)(ok ? row : m0) * D + k0 + cc[it], ok);
                cp_async16(bn + (cr[it] * HS + cc[it]) * 2,
                           W + (size_t)(n0 + cr[it]) * D + k0 + cc[it], 16);
            }
            cp_commit();
        }

        const unsigned ab = au + (buf * 128 * HS) * 2;
        const unsigned bb = bu + (buf * 128 * HS) * 2;
#pragma unroll
        for (int kk = 0; kk < 2; kk++) {
            unsigned a[4][4];
#pragma unroll
            for (int i = 0; i < 4; i++)
                ldsm_x4(a[i][0], a[i][1], a[i][2], a[i][3],
                        ab + ((wm + i * 16) * HS + kk * 16 + la) * 2);
#pragma unroll
            for (int j2 = 0; j2 < 2; j2++) {
                unsigned b0, b1, b2, b3;
                ldsm_x4(b0, b1, b2, b3,
                        bb + ((wn + j2 * 16) * HS + kk * 16 + lb) * 2);
#pragma unroll
                for (int i = 0; i < 4; i++) {
                    mma_f16(acc[i][2 * j2],     a[i][0], a[i][1], a[i][2], a[i][3], b0, b1);
                    mma_f16(acc[i][2 * j2 + 1], a[i][0], a[i][1], a[i][2], a[i][3], b2, b3);
                }
            }
        }
        __syncthreads();
    }

    // epilogue
#pragma unroll
    for (int j = 0; j < 4; j++) {
        int c0 = n0 + wn + j * 8 + t * 2;
        float b0v = bias ? bias[c0] : 0.f;
        float b1v = bias ? bias[c0 + 1] : 0.f;
#pragma unroll
        for (int i = 0; i < 4; i++) {
            int r0 = m0 + wm + i * 16 + g;
            int r1 = r0 + 8;
            if (r0 < M) {
                float px = (acc[i][j][0] + b0v) * scale;
                float py = (acc[i][j][1] + b1v) * scale;
                if (HALF_OUT)
                    *(__half2*)(Ch + (size_t)r0 * D + c0) = __floats2half2_rn(px, py);
                else
                    *(float2*)(Cf + (size_t)r0 * D + c0) = make_float2(px, py);
            }
            if (r1 < M) {
                float px = (acc[i][j][2] + b0v) * scale;
                float py = (acc[i][j][3] + b1v) * scale;
                if (HALF_OUT)
                    *(__half2*)(Ch + (size_t)r1 * D + c0) = __floats2half2_rn(px, py);
                else
                    *(float2*)(Cf + (size_t)r1 * D + c0) = make_float2(px, py);
            }
        }
    }
}

// Fused QKV: grid (6, 34, 3). y==33 is the det tile (rows 4201..4300).
__global__ void __launch_bounds__(256, 2) qkv_gemm(
    const __half* __restrict__ x, const __half* __restrict__ wh,
    const float* __restrict__ bq_p, const float* __restrict__ bq_d,
    const float* __restrict__ bv_p, const float* __restrict__ bv_d,
    __half* __restrict__ q, __half* __restrict__ k, __half* __restrict__ v)
{
    __shared__ GemmSmemH s;
    const bool det = (blockIdx.y == gridDim.y - 1);
    const int m0 = det ? NP : blockIdx.y * 128;
    const int M  = det ? N_TOK : NP;
    const int z = blockIdx.z;

    int wsel;
    const float* bias;
    __half* C;
    float scale = 1.f;
    if (z == 0) {
        wsel = det ? 1 : 0; bias = det ? bq_d : bq_p; C = q; scale = QSCALE;
    } else if (z == 1) {
        wsel = det ? 3 : 2; bias = nullptr; C = k;
    } else {
        wsel = det ? 5 : 4; bias = det ? bv_d : bv_p; C = v;
    }
    gemm_body_h<true>(x, wh + (size_t)wsel * WSZ, bias, nullptr, C,
                      m0, blockIdx.x * 128, M, scale, s);
}

// Fused out-projection: grid (6, 34). y==33 is the det tile.
__global__ void __launch_bounds__(256, 2) out_gemm(
    const __half* __restrict__ A, const __half* __restrict__ wh,
    const float* __restrict__ bo_p, const float* __restrict__ bo_d,
    float* __restrict__ C)
{
    __shared__ GemmSmemH s;
    const bool det = (blockIdx.y == gridDim.y - 1);
    const int m0 = det ? NP : blockIdx.y * 128;
    const int M  = det ? N_TOK : NP;
    gemm_body_h<false>(A, wh + (size_t)(det ? 7 : 6) * WSZ,
                       det ? bo_d : bo_p, C, nullptr,
                       m0, blockIdx.x * 128, M, 1.f, s);
}

// ---------------------------------------------------------------------------
// fp16 tensor-core flash attention (m16n8k16, fp32 accum).  [R8, unchanged]
// ---------------------------------------------------------------------------
#define KH 72
#define VH 72
#define NKT ((N_TOK + 63) / 64)
#define ATT_SMEM ((64 * KH + 2 * 64 * VH) * 2)

__global__ void __launch_bounds__(256, 2) attn_tc(
    const __half* __restrict__ q, const __half* __restrict__ k,
    const __half* __restrict__ v, float* __restrict__ o)
{
    extern __shared__ __half smh[];
    __half* Ks  = smh;                 // [64][KH]
    __half* Vs0 = smh + 64 * KH;       // [2][64][VH]

    const int h = blockIdx.y;
    const int q0 = blockIdx.x * 128;
    const int tid = threadIdx.x;
    const int w = tid >> 5;
    const int l = tid & 31;
    const int g = l >> 2;
    const int t = l & 3;
    const int wq = w * 16;
    const size_t hoff = (size_t)h * HD;

    int cr_[2], cc_[2];
#pragma unroll
    for (int it = 0; it < 2; it++) {
        int slot = tid + 256 * it;
        cr_[it] = slot >> 3;
        cc_[it] = (slot & 7) * 8;
    }
    unsigned ks_u = (unsigned)__cvta_generic_to_shared(Ks);
    unsigned vs_u = (unsigned)__cvta_generic_to_shared(Vs0);

#pragma unroll
    for (int it = 0; it < 2; it++) {
        cp_async16(ks_u + (cr_[it] * KH + cc_[it]) * 2,
                   k + (size_t)cr_[it] * D + hoff + cc_[it], 16);
        cp_async16(vs_u + (cr_[it] * VH + cc_[it]) * 2,
                   v + (size_t)cr_[it] * D + hoff + cc_[it], 16);
    }
    cp_commit();

    unsigned aq[4][4];
    {
        int gr0 = q0 + wq + g, gr1 = gr0 + 8;
        bool v0 = gr0 < N_TOK, v1 = gr1 < N_TOK;
        const __half* q0p = q + (size_t)gr0 * D + hoff;
        const __half* q1p = q + (size_t)gr1 * D + hoff;
#pragma unroll
        for (int s = 0; s < 4; s++) {
            int c0 = s * 16 + 2 * t;
            aq[s][0] = v0 ? *(const unsigned*)(q0p + c0) : 0u;
            aq[s][1] = v1 ? *(const unsigned*)(q1p + c0) : 0u;
            aq[s][2] = v0 ? *(const unsigned*)(q0p + c0 + 8) : 0u;
            aq[s][3] = v1 ? *(const unsigned*)(q1p + c0 + 8) : 0u;
        }
    }

    const int lk = (((l >> 4) << 3) + (l & 7)) * KH + ((l >> 3) & 1) * 8;
    const int lv = ((((l >> 3) & 1) << 3) + (l & 7)) * VH + ((l >> 4) << 3);

    float m0 = -1e30f, m1 = -1e30f, l0 = 0.f, l1 = 0.f;
    float oacc[8][4];
#pragma unroll
    for (int n = 0; n < 8; n++)
#pragma unroll
        for (int r = 0; r < 4; r++) oacc[n][r] = 0.f;

    for (int ti = 0; ti < NKT; ti++) {
        const int t0 = ti * 64;
        const int cnt = min(64, N_TOK - t0);
        const int buf = ti & 1;
        const unsigned vb_u = vs_u + buf * 64 * VH * 2;

        asm volatile("cp.async.wait_group 0;");
        __syncthreads();

        float sc[8][4];
#pragma unroll
        for (int n = 0; n < 8; n++)
#pragma unroll
            for (int r = 0; r < 4; r++) sc[n][r] = 0.f;

#pragma unroll
        for (int s = 0; s < 4; s++) {
#pragma unroll
            for (int np = 0; np < 4; np++) {
                unsigned b0, b1, b2, b3;
                ldsm_x4(b0, b1, b2, b3,
                        ks_u + (np * 16 * KH + s * 16 + lk) * 2);
                mma_f16(sc[2 * np],     aq[s][0], aq[s][1], aq[s][2], aq[s][3], b0, b1);
                mma_f16(sc[2 * np + 1], aq[s][0], aq[s][1], aq[s][2], aq[s][3], b2, b3);
            }
        }

        __syncthreads();
        if (ti + 1 < NKT) {
            const int nt0 = t0 + 64;
            const int ncnt = min(64, N_TOK - nt0);
            const unsigned vb2 = vs_u + (buf ^ 1) * 64 * VH * 2;
#pragma unroll
            for (int it = 0; it < 2; it++) {
                int row = cr_[it], cc = cc_[it];
                int ok = (row < ncnt) ? 16 : 0;
                size_t off = (size_t)(nt0 + (ok ? row : 0)) * D + hoff + cc;
                cp_async16(ks_u + (row * KH + cc) * 2, k + off, ok);
                cp_async16(vb2 + (row * VH + cc) * 2, v + off, ok);
            }
            cp_commit();
        }

        if (cnt < 64) {
#pragma unroll
            for (int n = 0; n < 8; n++) {
                int j0 = n * 8 + t * 2;
                if (j0 >= cnt)     { sc[n][0] = -1e30f; sc[n][2] = -1e30f; }
                if (j0 + 1 >= cnt) { sc[n][1] = -1e30f; sc[n][3] = -1e30f; }
            }
        }

        float mx0 = -1e30f, mx1 = -1e30f;
#pragma unroll
        for (int n = 0; n < 8; n++) {
            mx0 = fmaxf(mx0, fmaxf(sc[n][0], sc[n][1]));
            mx1 = fmaxf(mx1, fmaxf(sc[n][2], sc[n][3]));
        }
        mx0 = fmaxf(mx0, __shfl_xor_sync(0xffffffffu, mx0, 1));
        mx0 = fmaxf(mx0, __shfl_xor_sync(0xffffffffu, mx0, 2));
        mx1 = fmaxf(mx1, __shfl_xor_sync(0xffffffffu, mx1, 1));
        mx1 = fmaxf(mx1, __shfl_xor_sync(0xffffffffu, mx1, 2));
        float nm0 = fmaxf(m0, mx0), nm1 = fmaxf(m1, mx1);
        float esc0 = __expf(m0 - nm0), esc1 = __expf(m1 - nm1);
        m0 = nm0; m1 = nm1;

        float sum0 = 0.f, sum1 = 0.f;
#pragma unroll
        for (int n = 0; n < 8; n++) {
            sc[n][0] = __expf(sc[n][0] - m0);
            sc[n][1] = __expf(sc[n][1] - m0);
            sc[n][2] = __expf(sc[n][2] - m1);
            sc[n][3] = __expf(sc[n][3] - m1);
            sum0 += sc[n][0] + sc[n][1];
            sum1 += sc[n][2] + sc[n][3];
        }
        sum0 += __shfl_xor_sync(0xffffffffu, sum0, 1);
        sum0 += __shfl_xor_sync(0xffffffffu, sum0, 2);
        sum1 += __shfl_xor_sync(0xffffffffu, sum1, 1);
        sum1 += __shfl_xor_sync(0xffffffffu, sum1, 2);
        l0 = l0 * esc0 + sum0;
        l1 = l1 * esc1 + sum1;

        if (__any_sync(0xffffffffu, (esc0 != 1.f) || (esc1 != 1.f))) {
#pragma unroll
            for (int n = 0; n < 8; n++) {
                oacc[n][0] *= esc0; oacc[n][1] *= esc0;
                oacc[n][2] *= esc1; oacc[n][3] *= esc1;
            }
        }

#pragma unroll
        for (int s = 0; s < 4; s++) {
            unsigned a0 = packh2(sc[2 * s][0],     sc[2 * s][1]);
            unsigned a1 = packh2(sc[2 * s][2],     sc[2 * s][3]);
            unsigned a2 = packh2(sc[2 * s + 1][0], sc[2 * s + 1][1]);
            unsigned a3 = packh2(sc[2 * s + 1][2], sc[2 * s + 1][3]);
#pragma unroll
            for (int np = 0; np < 4; np++) {
                unsigned b0, b1, b2, b3;
                ldsm_x4_t(b0, b1, b2, b3,
                          vb_u + (s * 16 * VH + np * 16 + lv) * 2);
                mma_f16(oacc[2 * np],     a0, a1, a2, a3, b0, b1);
                mma_f16(oacc[2 * np + 1], a0, a1, a2, a3, b2, b3);
            }
        }
    }

    float i0 = 1.f / l0, i1 = 1.f / l1;
    int gr0 = q0 + wq + g, gr1 = gr0 + 8;
#pragma unroll
    for (int n = 0; n < 8; n++) {
        int c = h * HD + n * 8 + t * 2;
        if (gr0 < N_TOK) {
            float2 p;
            p.x = oacc[n][0] * i0; p.y = oacc[n][1] * i0;
            *(float2*)(o + (size_t)gr0 * D + c) = p;
        }
        if (gr1 < N_TOK) {
            float2 p;
            p.x = oacc[n][2] * i1; p.y = oacc[n][3] * i1;
            *(float2*)(o + (size_t)gr1 * D + c) = p;
        }
    }
}

// ---------------------------------------------------------------------------
// LayerNorm: reads fp32 attention output, writes fp16 for the out-projection.
// ---------------------------------------------------------------------------
__global__ void __launch_bounds__(256) ln_kernel(
    const float* __restrict__ o, __half* __restrict__ oh,
    const float* __restrict__ g, const float* __restrict__ b)
{
    const int row = blockIdx.x;
    const float* p = o + (size_t)row * D;
    __half* ph = oh + (size_t)row * D;
    const int t = threadIdx.x;
    float x0 = p[t], x1 = p[t + 256], x2 = p[t + 512];
    float s = x0 + x1 + x2;
    float sq = x0 * x0 + x1 * x1 + x2 * x2;

    __shared__ float red[64];
#pragma unroll
    for (int off = 16; off > 0; off >>= 1) {
        s  += __shfl_down_sync(0xffffffffu, s, off);
        sq += __shfl_down_sync(0xffffffffu, sq, off);
    }
    int wid = t >> 5, lid = t & 31;
    if (lid == 0) { red[wid] = s; red[wid + 32] = sq; }
    __syncthreads();
    __shared__ float mu_s, rstd_s;
    if (t == 0) {
        float S = 0.f, SQ = 0.f;
#pragma unroll
        for (int i = 0; i < 8; i++) { S += red[i]; SQ += red[i + 32]; }
        float mu = S * (1.f / D);
        float var = SQ * (1.f / D) - mu * mu;
        mu_s = mu;
        rstd_s = rsqrtf(var + 1e-5f);
    }
    __syncthreads();
    float mu = mu_s, r = rstd_s;
    ph[t]       = __float2half((x0 - mu) * r * g[t]       + b[t]);
    ph[t + 256] = __float2half((x1 - mu) * r * g[t + 256] + b[t + 256]);
    ph[t + 512] = __float2half((x2 - mu) * r * g[t + 512] + b[t + 512]);
}

// ---------------------------------------------------------------------------
extern "C" void kernel_launch(void* const* d_in, const int* in_sizes, int n_in,
                              void* d_out, int out_size)
{
    const float* x    = (const float*)d_in[0];
    const float* wq_p = (const float*)d_in[1];
    const float* wk_p = (const float*)d_in[2];
    const float* wv_p = (const float*)d_in[3];
    const float* wq_d = (const float*)d_in[4];
    const float* wk_d = (const float*)d_in[5];
    const float* wv_d = (const float*)d_in[6];
    const float* bq_p = (const float*)d_in[7];
    const float* bv_p = (const float*)d_in[8];
    const float* bq_d = (const float*)d_in[9];
    const float* bv_d = (const float*)d_in[10];
    const float* ln_g = (const float*)d_in[11];
    const float* ln_b = (const float*)d_in[12];
    const float* wo_p = (const float*)d_in[13];
    const float* bo_p = (const float*)d_in[14];
    const float* wo_d = (const float*)d_in[15];
    const float* bo_d = (const float*)d_in[16];
    float* out = (float*)d_out;

    __half *xh, *wh, *q, *k, *v, *oh;
    float *o;
    cudaGetSymbolAddress((void**)&xh, g_xh);
    cudaGetSymbolAddress((void**)&wh, g_wh);
    cudaGetSymbolAddress((void**)&q, g_q);
    cudaGetSymbolAddress((void**)&k, g_k);
    cudaGetSymbolAddress((void**)&v, g_v);
    cudaGetSymbolAddress((void**)&o, g_o);
    cudaGetSymbolAddress((void**)&oh, g_oh);

    cudaFuncSetAttribute(attn_tc, cudaFuncAttributeMaxDynamicSharedMemorySize, ATT_SMEM);

    // fp32 -> fp16 pre-passes
    const int nx = N_TOK * D;
    f2h_x<<<(nx / 8 + 255) / 256, 256>>>(x, xh, nx);
    dim3 gw(WSZ / 8 / 256, 8);
    w2h<<<gw, 256>>>(wq_p, wq_d, wk_p, wk_d, wv_p, wv_d, wo_p, wo_d, wh);

    // Fused QKV projections (fp16 tensor cores)
    dim3 gq(D / 128, 34, 3);
    qkv_gemm<<<gq, 256>>>(xh, wh, bq_p, bq_d, bv_p, bv_d, q, k, v);

    // Attention (fp16 tensor-core flash)
    dim3 ga((N_TOK + 127) / 128, H);
    attn_tc<<<ga, 256, ATT_SMEM>>>(q, k, v, o);

    // LayerNorm -> fp16
    ln_kernel<<<N_TOK, 256>>>(o, oh, ln_g, ln_b);

    // Output projection (fp16 tensor cores, fp32 out)
    dim3 go(D / 128, 34);
    out_gemm<<<go, 256>>>(oh, wh, bo_p, bo_d, out);
}